// round 3
// baseline (speedup 1.0000x reference)
#include <cuda_runtime.h>
#include <math.h>

#define B_  32
#define S_  1024
#define F0_ 2048
#define D_  768
#define L_  100
#define H_  8
#define HD_ 96
#define DF_ 10
#define C_  1000
#define BL_ (B_*L_)   // 3200
#define BS_ (B_*S_)   // 32768

// ---------------- scratch (static __device__, allocation-free) ----------------
static __device__ float g_t  [L_*D_];
static __device__ float g_q  [L_*D_];
static __device__ float g_mem[(size_t)BS_*D_];
static __device__ float g_k  [(size_t)BS_*D_];
static __device__ float g_v  [(size_t)BS_*D_];
static __device__ float g_attn[(size_t)B_*H_*L_*S_];
static __device__ float g_ao [(size_t)BL_*D_];
static __device__ float g_x2 [(size_t)BL_*D_];
static __device__ float g_t2 [(size_t)BL_*D_];
static __device__ float g_f1 [(size_t)BL_*D_];
static __device__ float g_x3 [(size_t)BL_*D_];
static __device__ float g_h  [(size_t)BL_*D_];
static __device__ float g_yt [C_];
static __device__ float g_ascdump[(size_t)B_*L_*S_];  // fallback sink if out_size is small

// ---------------- block reductions (256 threads = 8 warps) ----------------
__device__ __forceinline__ float blockSum256(float v, float* sm) {
    #pragma unroll
    for (int o = 16; o > 0; o >>= 1) v += __shfl_xor_sync(0xffffffffu, v, o);
    const int w = threadIdx.x >> 5, lane = threadIdx.x & 31;
    if (lane == 0) sm[w] = v;
    __syncthreads();
    float r = (lane < 8) ? sm[lane] : 0.0f;
    #pragma unroll
    for (int o = 4; o > 0; o >>= 1) r += __shfl_xor_sync(0xffffffffu, r, o);
    r = __shfl_sync(0xffffffffu, r, 0);
    __syncthreads();
    return r;
}

__device__ __forceinline__ float blockMax256(float v, float* sm) {
    #pragma unroll
    for (int o = 16; o > 0; o >>= 1) v = fmaxf(v, __shfl_xor_sync(0xffffffffu, v, o));
    const int w = threadIdx.x >> 5, lane = threadIdx.x & 31;
    if (lane == 0) sm[w] = v;
    __syncthreads();
    float r = (lane < 8) ? sm[lane] : -INFINITY;
    #pragma unroll
    for (int o = 4; o > 0; o >>= 1) r = fmaxf(r, __shfl_xor_sync(0xffffffffu, r, o));
    r = __shfl_sync(0xffffffffu, r, 0);
    __syncthreads();
    return r;
}

// ---------------- generic NT GEMM:  C = act(A * B^T + bias [+ res]) ----------------
// A: (M,K) row-major, Bw: (N,K) row-major. M%128==0, N%128==0, K%16==0.
// RES: 0 none, 1 full (M,N), 2 broadcast row Res[m % resMod]
#define GBM 128
#define GBN 128
#define GBK 16

template<bool RELU, int RES>
__global__ __launch_bounds__(256)
void gemm_nt(const float* __restrict__ A, const float* __restrict__ Bw,
             const float* __restrict__ bias, const float* __restrict__ Res,
             float* __restrict__ C, int M, int N, int K, int resMod)
{
    __shared__ float As[GBK][GBM + 1];
    __shared__ float Bs[GBK][GBN + 1];
    const int bm = blockIdx.y * GBM;
    const int bn = blockIdx.x * GBN;
    const int tid = threadIdx.x;
    const int ty = tid >> 4;      // 0..15
    const int tx = tid & 15;      // 0..15

    float acc[8][8];
    #pragma unroll
    for (int i = 0; i < 8; i++)
        #pragma unroll
        for (int j = 0; j < 8; j++) acc[i][j] = 0.0f;

    const int lr = tid >> 2;            // 0..63
    const int lc = (tid & 3) * 4;       // 0,4,8,12

    for (int k0 = 0; k0 < K; k0 += GBK) {
        #pragma unroll
        for (int half = 0; half < 2; half++) {
            const int r = lr + half * 64;
            float4 fa = *(const float4*)(A  + (size_t)(bm + r) * K + k0 + lc);
            As[lc + 0][r] = fa.x; As[lc + 1][r] = fa.y;
            As[lc + 2][r] = fa.z; As[lc + 3][r] = fa.w;
            float4 fb = *(const float4*)(Bw + (size_t)(bn + r) * K + k0 + lc);
            Bs[lc + 0][r] = fb.x; Bs[lc + 1][r] = fb.y;
            Bs[lc + 2][r] = fb.z; Bs[lc + 3][r] = fb.w;
        }
        __syncthreads();
        #pragma unroll
        for (int kk = 0; kk < GBK; kk++) {
            float ra[8], rb[8];
            #pragma unroll
            for (int i = 0; i < 8; i++) ra[i] = As[kk][ty * 8 + i];
            #pragma unroll
            for (int j = 0; j < 8; j++) rb[j] = Bs[kk][tx * 8 + j];
            #pragma unroll
            for (int i = 0; i < 8; i++)
                #pragma unroll
                for (int j = 0; j < 8; j++)
                    acc[i][j] = fmaf(ra[i], rb[j], acc[i][j]);
        }
        __syncthreads();
    }

    #pragma unroll
    for (int i = 0; i < 8; i++) {
        const int m = bm + ty * 8 + i;
        const float* resRow = (RES == 1) ? (Res + (size_t)m * N)
                            : (RES == 2) ? (Res + (size_t)(m % resMod) * N)
                            : nullptr;
        #pragma unroll
        for (int j = 0; j < 8; j++) {
            const int n = bn + tx * 8 + j;
            float v = acc[i][j] + bias[n];
            if (RES != 0) v += resRow[n];
            if (RELU) v = fmaxf(v, 0.0f);
            C[(size_t)m * N + n] = v;
        }
    }
}

// ---------------- row LayerNorm over D_=768, input pre-scaled by alpha ----------------
__global__ void ln_rows(const float* __restrict__ X, const float* __restrict__ gg,
                        const float* __restrict__ bb, float* __restrict__ O, float alpha)
{
    __shared__ float sm[8];
    const int row = blockIdx.x;
    const float* x = X + (size_t)row * D_;
    float v[3];
    float s = 0.0f, sq = 0.0f;
    #pragma unroll
    for (int j = 0; j < 3; j++) {
        v[j] = alpha * x[threadIdx.x + j * 256];
        s += v[j]; sq += v[j] * v[j];
    }
    s  = blockSum256(s, sm);
    sq = blockSum256(sq, sm);
    const float mean = s * (1.0f / D_);
    const float var  = sq * (1.0f / D_) - mean * mean;
    const float inv  = rsqrtf(var + 1e-5f);
    float* o = O + (size_t)row * D_;
    #pragma unroll
    for (int j = 0; j < 3; j++) {
        const int i = threadIdx.x + j * 256;
        o[i] = (v[j] - mean) * inv * gg[i] + bb[i];
    }
}

// ---------------- q projection (L=100 rows), folds 1/sqrt(hd) ----------------
__global__ void qproj(const float* __restrict__ t, const float* __restrict__ Wq,
                      const float* __restrict__ bq, float* __restrict__ q)
{
    const int l = blockIdx.x;
    const int e = blockIdx.y * 128 + threadIdx.x;
    __shared__ float ts[D_];
    for (int i = threadIdx.x; i < D_; i += 128) ts[i] = t[(size_t)l * D_ + i];
    __syncthreads();
    const float* w = Wq + (size_t)e * D_;
    float acc = 0.0f;
    #pragma unroll 8
    for (int d = 0; d < D_; d++) acc = fmaf(ts[d], w[d], acc);
    q[(size_t)l * D_ + e] = (acc + bq[e]) * 0.10206207261596575f;  // 1/sqrt(96)
}

// ---------------- scores: attn[b,h,l,s] = q_h[l,:] . k[b,s,h,:] (scale folded into q) ----
__global__ __launch_bounds__(128)
void scores_kernel(const float* __restrict__ q, const float* __restrict__ k,
                   float* __restrict__ attn)
{
    const int bh = blockIdx.y, b = bh >> 3, h = bh & 7;
    const int s = blockIdx.x * 128 + threadIdx.x;
    __shared__ float qs[L_ * HD_];
    for (int idx = threadIdx.x; idx < L_ * HD_; idx += 128) {
        const int l = idx / HD_, e = idx - l * HD_;
        qs[idx] = q[(size_t)l * D_ + h * HD_ + e];
    }
    __syncthreads();
    const float4* kr4 = (const float4*)(k + ((size_t)b * S_ + s) * D_ + h * HD_);
    float4 kreg[HD_ / 4];
    #pragma unroll
    for (int e4 = 0; e4 < HD_ / 4; e4++) kreg[e4] = kr4[e4];

    float* orow = attn + (size_t)bh * L_ * S_ + s;
    for (int l0 = 0; l0 < L_; l0 += 20) {
        float acc[20];
        #pragma unroll
        for (int i = 0; i < 20; i++) acc[i] = 0.0f;
        #pragma unroll
        for (int i = 0; i < 20; i++) {
            const float* qrow = &qs[(size_t)(l0 + i) * HD_];
            #pragma unroll
            for (int e4 = 0; e4 < HD_ / 4; e4++) {
                const float4 qq = *(const float4*)&qrow[e4 * 4];
                const float4 kk = kreg[e4];
                acc[i] = fmaf(qq.x, kk.x, acc[i]);
                acc[i] = fmaf(qq.y, kk.y, acc[i]);
                acc[i] = fmaf(qq.z, kk.z, acc[i]);
                acc[i] = fmaf(qq.w, kk.w, acc[i]);
            }
        }
        #pragma unroll
        for (int i = 0; i < 20; i++) orow[(size_t)(l0 + i) * S_] = acc[i];
    }
}

// ---------------- softmax in place + head-mean a_score ----------------
__global__ void softmax_mean(float* __restrict__ attn, float* __restrict__ ascore)
{
    __shared__ float sm[8];
    const int l = blockIdx.x, b = blockIdx.y;
    const int tid = threadIdx.x;
    float am[4] = {0.f, 0.f, 0.f, 0.f};
    for (int h = 0; h < H_; h++) {
        float* row = attn + (((size_t)(b * H_ + h)) * L_ + l) * S_;
        float v[4];
        float mx = -INFINITY;
        #pragma unroll
        for (int j = 0; j < 4; j++) { v[j] = row[tid + j * 256]; mx = fmaxf(mx, v[j]); }
        mx = blockMax256(mx, sm);
        float ssum = 0.0f;
        #pragma unroll
        for (int j = 0; j < 4; j++) { v[j] = expf(v[j] - mx); ssum += v[j]; }
        ssum = blockSum256(ssum, sm);
        const float inv = 1.0f / ssum;
        #pragma unroll
        for (int j = 0; j < 4; j++) {
            const float p = v[j] * inv;
            row[tid + j * 256] = p;
            am[j] += p * (1.0f / H_);
        }
    }
    float* ao = ascore + ((size_t)b * L_ + l) * S_;
    #pragma unroll
    for (int j = 0; j < 4; j++) ao[tid + j * 256] = am[j];
}

// ---------------- ao[b,l,h,:] = attn[b,h,l,:] @ v[b,:,h,:] ----------------
#define AV_ST 32
__global__ __launch_bounds__(256)
void attn_v(const float* __restrict__ attn, const float* __restrict__ v,
            float* __restrict__ ao)
{
    const int bh = blockIdx.x, b = bh >> 3, h = bh & 7;
    const float* A = attn + (size_t)bh * L_ * S_;
    const float* V = v + (size_t)b * S_ * D_ + h * HD_;
    __shared__ float As[AV_ST][113];   // [ss][m], m padded 100->113 (zero)
    __shared__ float Vs[AV_ST][HD_];
    const int tid = threadIdx.x;
    const int tx = tid & 15, ty = tid >> 4;
    float acc[7][6];
    #pragma unroll
    for (int i = 0; i < 7; i++)
        #pragma unroll
        for (int j = 0; j < 6; j++) acc[i][j] = 0.0f;

    for (int idx = tid; idx < AV_ST * 13; idx += 256)
        As[idx / 13][100 + idx % 13] = 0.0f;     // pad stays zero (loads never touch it)

    for (int s0 = 0; s0 < S_; s0 += AV_ST) {
        for (int idx = tid; idx < L_ * AV_ST; idx += 256) {
            const int m = idx / AV_ST, ss = idx - m * AV_ST;
            As[ss][m] = A[(size_t)m * S_ + s0 + ss];
        }
        for (int idx = tid; idx < AV_ST * HD_; idx += 256) {
            const int r = idx / HD_, c = idx - r * HD_;
            Vs[r][c] = V[(size_t)(s0 + r) * D_ + c];
        }
        __syncthreads();
        #pragma unroll 4
        for (int ss = 0; ss < AV_ST; ss++) {
            float ra[7], rb[6];
            #pragma unroll
            for (int i = 0; i < 7; i++) ra[i] = As[ss][ty + 16 * i];
            #pragma unroll
            for (int j = 0; j < 6; j++) rb[j] = Vs[ss][tx + 16 * j];
            #pragma unroll
            for (int i = 0; i < 7; i++)
                #pragma unroll
                for (int j = 0; j < 6; j++)
                    acc[i][j] = fmaf(ra[i], rb[j], acc[i][j]);
        }
        __syncthreads();
    }
    #pragma unroll
    for (int i = 0; i < 7; i++) {
        const int m = ty + 16 * i;
        if (m < L_) {
            float* orow = ao + ((size_t)b * L_ + m) * D_ + h * HD_;
            #pragma unroll
            for (int j = 0; j < 6; j++) orow[tx + 16 * j] = acc[i][j];
        }
    }
}

// ---------------- GroupFC batch-independent term + bias ----------------
__global__ void yterm_kernel(const float* __restrict__ y, const float* __restrict__ dp,
                             const float* __restrict__ dbias, float* __restrict__ yt)
{
    const int l = blockIdx.x;
    const int w = threadIdx.x >> 5, lane = threadIdx.x & 31;   // 10 warps
    const float* dpl = dp + (size_t)l * (2 * D_) * DF_ + (size_t)D_ * DF_ + w;
    const float* yr = y + (size_t)l * D_;
    float acc = 0.0f;
    for (int d = lane; d < D_; d += 32) acc = fmaf(yr[d], dpl[(size_t)d * DF_], acc);
    #pragma unroll
    for (int o = 16; o > 0; o >>= 1) acc += __shfl_xor_sync(0xffffffffu, acc, o);
    if (lane == 0) yt[l * DF_ + w] = acc + dbias[l * DF_ + w];
}

// ---------------- logits[b, l*10+f] = h[b,l,:] . dup_pool[l,:768,f] + yterm ----------------
__global__ void logits_kernel(const float* __restrict__ hh, const float* __restrict__ dp,
                              const float* __restrict__ yt, float* __restrict__ out)
{
    const int l = blockIdx.x, b = blockIdx.y;
    const int w = threadIdx.x >> 5, lane = threadIdx.x & 31;   // 10 warps
    __shared__ float hs[D_];
    for (int i = threadIdx.x; i < D_; i += 320) hs[i] = hh[((size_t)b * L_ + l) * D_ + i];
    __syncthreads();
    const float* dpl = dp + (size_t)l * (2 * D_) * DF_ + w;
    float acc = 0.0f;
    for (int d = lane; d < D_; d += 32) acc = fmaf(hs[d], dpl[(size_t)d * DF_], acc);
    #pragma unroll
    for (int o = 16; o > 0; o >>= 1) acc += __shfl_xor_sync(0xffffffffu, acc, o);
    if (lane == 0) out[(size_t)b * C_ + l * DF_ + w] = acc + yt[l * DF_ + w];
}

// ---------------- host launch ----------------
extern "C" void kernel_launch(void* const* d_in, const int* in_sizes, int n_in,
                              void* d_out, int out_size)
{
    const float* x       = (const float*)d_in[0];
    const float* y       = (const float*)d_in[1];
    const float* embed_W = (const float*)d_in[2];
    const float* embed_b = (const float*)d_in[3];
    const float* Wq      = (const float*)d_in[4];
    const float* Wk      = (const float*)d_in[5];
    const float* Wv      = (const float*)d_in[6];
    const float* bq      = (const float*)d_in[7];
    const float* bk      = (const float*)d_in[8];
    const float* bv      = (const float*)d_in[9];
    const float* Wo      = (const float*)d_in[10];
    const float* bo      = (const float*)d_in[11];
    const float* ln1_g   = (const float*)d_in[12];
    const float* ln1_b   = (const float*)d_in[13];
    const float* ln2_g   = (const float*)d_in[14];
    const float* ln2_b   = (const float*)d_in[15];
    const float* ln3_g   = (const float*)d_in[16];
    const float* ln3_b   = (const float*)d_in[17];
    const float* W1      = (const float*)d_in[18];
    const float* b1      = (const float*)d_in[19];
    const float* W2      = (const float*)d_in[20];
    const float* b2      = (const float*)d_in[21];
    const float* dp      = (const float*)d_in[22];
    const float* dbias   = (const float*)d_in[23];
    float* out = (float*)d_out;

    float *pt, *pq, *pmem, *pk, *pv, *pattn, *pao, *px2, *pt2, *pf1, *px3, *ph, *pyt, *pdump;
    cudaGetSymbolAddress((void**)&pt,    g_t);
    cudaGetSymbolAddress((void**)&pq,    g_q);
    cudaGetSymbolAddress((void**)&pmem,  g_mem);
    cudaGetSymbolAddress((void**)&pk,    g_k);
    cudaGetSymbolAddress((void**)&pv,    g_v);
    cudaGetSymbolAddress((void**)&pattn, g_attn);
    cudaGetSymbolAddress((void**)&pao,   g_ao);
    cudaGetSymbolAddress((void**)&px2,   g_x2);
    cudaGetSymbolAddress((void**)&pt2,   g_t2);
    cudaGetSymbolAddress((void**)&pf1,   g_f1);
    cudaGetSymbolAddress((void**)&px3,   g_x3);
    cudaGetSymbolAddress((void**)&ph,    g_h);
    cudaGetSymbolAddress((void**)&pyt,   g_yt);
    cudaGetSymbolAddress((void**)&pdump, g_ascdump);

    // output layout: logits (B,1000) then a_score (B,L,S); guard against a smaller out
    float* asc = (out_size >= B_ * C_ + B_ * L_ * S_) ? (out + B_ * C_) : pdump;

    // batch-independent preamble
    ln_rows<<<L_, 256>>>(y, ln1_g, ln1_b, pt, 2.0f);                       // t = LN(2y)
    qproj<<<dim3(L_, D_ / 128), 128>>>(pt, Wq, bq, pq);                    // q (scaled)
    yterm_kernel<<<L_, 320>>>(y, dp, dbias, pyt);

    // mem = relu(x @ We^T + eb)
    gemm_nt<true, 0><<<dim3(D_ / 128, BS_ / 128), 256>>>(x, embed_W, embed_b, nullptr,
                                                         pmem, BS_, D_, F0_, 0);
    // k, v
    gemm_nt<false, 0><<<dim3(D_ / 128, BS_ / 128), 256>>>(pmem, Wk, bk, nullptr,
                                                          pk, BS_, D_, D_, 0);
    gemm_nt<false, 0><<<dim3(D_ / 128, BS_ / 128), 256>>>(pmem, Wv, bv, nullptr,
                                                          pv, BS_, D_, D_, 0);
    // attention
    scores_kernel<<<dim3(S_ / 128, B_ * H_), 128>>>(pq, pk, pattn);
    softmax_mean<<<dim3(L_, B_), 256>>>(pattn, asc);
    attn_v<<<B_ * H_, 256>>>(pattn, pv, pao);

    // out-proj + residual t[l], then LN2
    gemm_nt<false, 2><<<dim3(D_ / 128, BL_ / 128), 256>>>(pao, Wo, bo, pt,
                                                          px2, BL_, D_, D_, L_);
    ln_rows<<<BL_, 256>>>(px2, ln2_g, ln2_b, pt2, 1.0f);

    // FFN + residual, LN3
    gemm_nt<true, 0><<<dim3(D_ / 128, BL_ / 128), 256>>>(pt2, W1, b1, nullptr,
                                                         pf1, BL_, D_, D_, 0);
    gemm_nt<false, 1><<<dim3(D_ / 128, BL_ / 128), 256>>>(pf1, W2, b2, pt2,
                                                          px3, BL_, D_, D_, 0);
    ln_rows<<<BL_, 256>>>(px3, ln3_g, ln3_b, ph, 1.0f);

    // GroupFC logits
    logits_kernel<<<dim3(L_, B_), 320>>>(ph, dp, pyt, out);
}

// round 7
// speedup vs baseline: 2.1299x; 2.1299x over previous
#include <cuda_runtime.h>
#include <cuda_bf16.h>
#include <math.h>
#include <stdint.h>

#define B_  32
#define S_  1024
#define F0_ 2048
#define D_  768
#define L_  100
#define H_  8
#define HD_ 96
#define DF_ 10
#define C_  1000
#define BL_ (B_*L_)   // 3200
#define BS_ (B_*S_)   // 32768

// ---------------- scratch (static __device__, allocation-free) ----------------
static __device__ __align__(128) float g_t  [L_*D_];
static __device__ __align__(128) float g_q  [L_*D_];
static __device__ __align__(128) float g_mem[(size_t)BS_*D_];
static __device__ __align__(128) float g_k  [(size_t)BS_*D_];
static __device__ __align__(128) float g_v  [(size_t)BS_*D_];
static __device__ __align__(128) float g_attn[(size_t)B_*H_*L_*S_];
static __device__ __align__(128) float g_ao [(size_t)BL_*D_];
static __device__ __align__(128) float g_x2 [(size_t)BL_*D_];
static __device__ __align__(128) float g_t2 [(size_t)BL_*D_];
static __device__ __align__(128) float g_f1 [(size_t)BL_*D_];
static __device__ __align__(128) float g_x3 [(size_t)BL_*D_];
static __device__ __align__(128) float g_h  [(size_t)BL_*D_];
static __device__ __align__(128) float g_yt [C_];
static __device__ __align__(128) float g_ascdump[(size_t)B_*L_*S_];

// ============================================================================
// Baseline-PTX tensor core helpers (sm_80-era, safe on compute_103 PTX target)
// ============================================================================
__device__ __forceinline__ uint32_t smem_u32(const void* p) {
    uint32_t a;
    asm("{ .reg .u64 t; cvta.to.shared.u64 t, %1; cvt.u32.u64 %0, t; }" : "=r"(a) : "l"(p));
    return a;
}

#define LDSM4(r, addr)                                                            \
    asm volatile("ldmatrix.sync.aligned.m8n8.x4.shared.b16 {%0,%1,%2,%3}, [%4];"  \
        : "=r"((r)[0]), "=r"((r)[1]), "=r"((r)[2]), "=r"((r)[3]) : "r"(addr))

#define LDSM2(r, addr)                                                            \
    asm volatile("ldmatrix.sync.aligned.m8n8.x2.shared.b16 {%0,%1}, [%2];"        \
        : "=r"((r)[0]), "=r"((r)[1]) : "r"(addr))

#define MMA16816(c, a, b)                                                         \
    asm volatile("mma.sync.aligned.m16n8k16.row.col.f32.bf16.bf16.f32 "           \
        "{%0,%1,%2,%3}, {%4,%5,%6,%7}, {%8,%9}, {%0,%1,%2,%3};"                   \
        : "+f"((c)[0]), "+f"((c)[1]), "+f"((c)[2]), "+f"((c)[3])                  \
        : "r"((a)[0]), "r"((a)[1]), "r"((a)[2]), "r"((a)[3]),                     \
          "r"((b)[0]), "r"((b)[1]))

// fp32x16 -> bf16 hi (16) + bf16 lo (16), stored as 2x uint4 each
__device__ __forceinline__ void cvt_store(char* dst_hi, char* dst_lo, const float4* v) {
    uint32_t hi[8], lo[8];
    #pragma unroll
    for (int j = 0; j < 4; j++) {
        float4 f = v[j];
        __nv_bfloat162 h0 = __floats2bfloat162_rn(f.x, f.y);
        __nv_bfloat162 h1 = __floats2bfloat162_rn(f.z, f.w);
        float2 r0 = __bfloat1622float2(h0);
        float2 r1 = __bfloat1622float2(h1);
        __nv_bfloat162 l0 = __floats2bfloat162_rn(f.x - r0.x, f.y - r0.y);
        __nv_bfloat162 l1 = __floats2bfloat162_rn(f.z - r1.x, f.w - r1.y);
        hi[j*2+0] = *(uint32_t*)&h0; hi[j*2+1] = *(uint32_t*)&h1;
        lo[j*2+0] = *(uint32_t*)&l0; lo[j*2+1] = *(uint32_t*)&l1;
    }
    *(uint4*)(dst_hi)      = make_uint4(hi[0], hi[1], hi[2], hi[3]);
    *(uint4*)(dst_hi + 16) = make_uint4(hi[4], hi[5], hi[6], hi[7]);
    *(uint4*)(dst_lo)      = make_uint4(lo[0], lo[1], lo[2], lo[3]);
    *(uint4*)(dst_lo + 16) = make_uint4(lo[4], lo[5], lo[6], lo[7]);
}

// ============================================================================
// 3xBF16 HMMA GEMM:  C = act(A * B^T + bias [+ res])
// A: (M,K) fp32 row-major; Bw: (N,K) fp32 row-major. M%128==0, N%128==0, K%32==0.
// RES: 0 none, 1 full (M,N), 2 broadcast Res[m % resMod]
// Tile 128x128, BK=32, double-buffered SMEM (80B padded rows), 8 warps (2x4),
// warp tile 64x32, mma.m16n8k16.bf16 with hi/lo error-compensated 3-pass.
// ============================================================================
// smem per buffer: Ahi@0, Alo@10240, Bhi@20480, Blo@30720 (128 rows x 80B each)
#define GM_BUF  40960
#define GM_SMEM (2*GM_BUF)   // 81920

template<bool RELU, int RES>
__global__ __launch_bounds__(256)
void gemm_hmma(const float* __restrict__ A, const float* __restrict__ Bw,
               const float* __restrict__ bias, const float* __restrict__ Res,
               float* __restrict__ C, int M, int N, int K, int resMod)
{
    extern __shared__ char smem[];
    const int tid  = threadIdx.x;
    const int lane = tid & 31, wid = tid >> 5;
    const int bm = blockIdx.y * 128, bn = blockIdx.x * 128;
    const int wm = wid & 1, wn = wid >> 1;          // 2 x 4 warp grid
    const int row = tid >> 1, half = tid & 1;       // staging: 128 rows x 2 halves
    const uint32_t sb = smem_u32(smem);

    float c[4][4][4];
    #pragma unroll
    for (int mt = 0; mt < 4; mt++)
        #pragma unroll
        for (int nt = 0; nt < 4; nt++)
            #pragma unroll
            for (int q = 0; q < 4; q++) c[mt][nt][q] = 0.0f;

    const float* ap = A  + (size_t)(bm + row) * K + half * 16;
    const float* bp = Bw + (size_t)(bn + row) * K + half * 16;
    const int nIter = K >> 5;

    float4 ra[4], rb[4];
    // prologue: chunk 0 -> buffer 0
    #pragma unroll
    for (int j = 0; j < 4; j++) {
        ra[j] = *(const float4*)(ap + j * 4);
        rb[j] = *(const float4*)(bp + j * 4);
    }
    {
        char* d = smem + row * 80 + half * 32;
        cvt_store(d, d + 10240, ra);
        cvt_store(d + 20480, d + 30720, rb);
    }
    __syncthreads();

    // ldmatrix base addresses (per warp)
    const uint32_t aAddr0 = sb + (uint32_t)((wm * 64 + (lane & 15)) * 80 + (lane >> 4) * 16);
    const uint32_t bAddr0 = sb + 20480u + (uint32_t)((wn * 32 + (lane & 7)) * 80 + ((lane >> 3) & 1) * 16);

    for (int i = 0; i < nIter; i++) {
        const uint32_t bo = (uint32_t)(i & 1) * GM_BUF;

        // issue gmem loads for chunk i+1 early (hide DRAM latency under MMA)
        if (i + 1 < nIter) {
            const float* ap2 = ap + (i + 1) * 32;
            const float* bp2 = bp + (i + 1) * 32;
            #pragma unroll
            for (int j = 0; j < 4; j++) {
                ra[j] = *(const float4*)(ap2 + j * 4);
                rb[j] = *(const float4*)(bp2 + j * 4);
            }
        }

        // MMA on buffer i&1  (2 k16 steps, 3 passes: AhBh, AhBl, AlBh)
        #pragma unroll
        for (int ks = 0; ks < 2; ks++) {
            uint32_t aH[4][4], aL[4][4], bH[4][2], bL[4][2];
            #pragma unroll
            for (int mt = 0; mt < 4; mt++) {
                LDSM4(aH[mt], aAddr0 + bo + (uint32_t)(mt * 1280 + ks * 32));
                LDSM4(aL[mt], aAddr0 + bo + 10240u + (uint32_t)(mt * 1280 + ks * 32));
            }
            #pragma unroll
            for (int nt = 0; nt < 4; nt++) {
                LDSM2(bH[nt], bAddr0 + bo + (uint32_t)(nt * 640 + ks * 32));
                LDSM2(bL[nt], bAddr0 + bo + 10240u + (uint32_t)(nt * 640 + ks * 32));
            }
            #pragma unroll
            for (int mt = 0; mt < 4; mt++)
                #pragma unroll
                for (int nt = 0; nt < 4; nt++) {
                    MMA16816(c[mt][nt], aH[mt], bH[nt]);
                    MMA16816(c[mt][nt], aH[mt], bL[nt]);
                    MMA16816(c[mt][nt], aL[mt], bH[nt]);
                }
        }

        // convert + store chunk i+1 into the other buffer
        if (i + 1 < nIter) {
            char* d = smem + ((i + 1) & 1) * GM_BUF + row * 80 + half * 32;
            cvt_store(d, d + 10240, ra);
            cvt_store(d + 20480, d + 30720, rb);
        }
        __syncthreads();
    }

    // epilogue: frag (mt,nt): c0,c1 -> (m0, n0..1), c2,c3 -> (m0+8, n0..1)
    #pragma unroll
    for (int mt = 0; mt < 4; mt++) {
        const int m0 = bm + wm * 64 + mt * 16 + (lane >> 2);
        #pragma unroll
        for (int hh = 0; hh < 2; hh++) {
            const int m = m0 + hh * 8;
            const float* resRow = (RES == 1) ? (Res + (size_t)m * N)
                                : (RES == 2) ? (Res + (size_t)(m % resMod) * N)
                                : nullptr;
            #pragma unroll
            for (int nt = 0; nt < 4; nt++) {
                const int n = bn + wn * 32 + nt * 8 + (lane & 3) * 2;
                float2 o;
                o.x = c[mt][nt][hh * 2 + 0] + bias[n + 0];
                o.y = c[mt][nt][hh * 2 + 1] + bias[n + 1];
                if (RES != 0) { o.x += resRow[n + 0]; o.y += resRow[n + 1]; }
                if (RELU)     { o.x = fmaxf(o.x, 0.f); o.y = fmaxf(o.y, 0.f); }
                *(float2*)(C + (size_t)m * N + n) = o;
            }
        }
    }
}

// ---------------- block reductions (256 threads = 8 warps) ----------------
__device__ __forceinline__ float blockSum256(float v, float* sm) {
    #pragma unroll
    for (int o = 16; o > 0; o >>= 1) v += __shfl_xor_sync(0xffffffffu, v, o);
    const int w = threadIdx.x >> 5, lane = threadIdx.x & 31;
    if (lane == 0) sm[w] = v;
    __syncthreads();
    float r = (lane < 8) ? sm[lane] : 0.0f;
    #pragma unroll
    for (int o = 4; o > 0; o >>= 1) r += __shfl_xor_sync(0xffffffffu, r, o);
    r = __shfl_sync(0xffffffffu, r, 0);
    __syncthreads();
    return r;
}
__device__ __forceinline__ float blockMax256(float v, float* sm) {
    #pragma unroll
    for (int o = 16; o > 0; o >>= 1) v = fmaxf(v, __shfl_xor_sync(0xffffffffu, v, o));
    const int w = threadIdx.x >> 5, lane = threadIdx.x & 31;
    if (lane == 0) sm[w] = v;
    __syncthreads();
    float r = (lane < 8) ? sm[lane] : -INFINITY;
    #pragma unroll
    for (int o = 4; o > 0; o >>= 1) r = fmaxf(r, __shfl_xor_sync(0xffffffffu, r, o));
    r = __shfl_sync(0xffffffffu, r, 0);
    __syncthreads();
    return r;
}

// ---------------- row LayerNorm over D_=768, input pre-scaled by alpha ----------------
__global__ void ln_rows(const float* __restrict__ X, const float* __restrict__ gg,
                        const float* __restrict__ bb, float* __restrict__ O, float alpha)
{
    __shared__ float sm[8];
    const int row = blockIdx.x;
    const float* x = X + (size_t)row * D_;
    float v[3];
    float s = 0.0f, sq = 0.0f;
    #pragma unroll
    for (int j = 0; j < 3; j++) {
        v[j] = alpha * x[threadIdx.x + j * 256];
        s += v[j]; sq += v[j] * v[j];
    }
    s  = blockSum256(s, sm);
    sq = blockSum256(sq, sm);
    const float mean = s * (1.0f / D_);
    const float var  = sq * (1.0f / D_) - mean * mean;
    const float inv  = rsqrtf(var + 1e-5f);
    float* o = O + (size_t)row * D_;
    #pragma unroll
    for (int j = 0; j < 3; j++) {
        const int i = threadIdx.x + j * 256;
        o[i] = (v[j] - mean) * inv * gg[i] + bb[i];
    }
}

// ---------------- q projection (L=100 rows), folds 1/sqrt(hd) ----------------
__global__ void qproj(const float* __restrict__ t, const float* __restrict__ Wq,
                      const float* __restrict__ bq, float* __restrict__ q)
{
    const int l = blockIdx.x;
    const int e = blockIdx.y * 128 + threadIdx.x;
    __shared__ float ts[D_];
    for (int i = threadIdx.x; i < D_; i += 128) ts[i] = t[(size_t)l * D_ + i];
    __syncthreads();
    const float* w = Wq + (size_t)e * D_;
    float acc = 0.0f;
    #pragma unroll 8
    for (int d = 0; d < D_; d++) acc = fmaf(ts[d], w[d], acc);
    q[(size_t)l * D_ + e] = (acc + bq[e]) * 0.10206207261596575f;  // 1/sqrt(96)
}

// ---------------- scores: attn[b,h,l,s] = q_h[l,:] . k[b,s,h,:] ----------------
__global__ __launch_bounds__(128)
void scores_kernel(const float* __restrict__ q, const float* __restrict__ k,
                   float* __restrict__ attn)
{
    const int bh = blockIdx.y, b = bh >> 3, h = bh & 7;
    const int s = blockIdx.x * 128 + threadIdx.x;
    __shared__ float qs[L_ * HD_];
    for (int idx = threadIdx.x; idx < L_ * HD_; idx += 128) {
        const int l = idx / HD_, e = idx - l * HD_;
        qs[idx] = q[(size_t)l * D_ + h * HD_ + e];
    }
    __syncthreads();
    const float4* kr4 = (const float4*)(k + ((size_t)b * S_ + s) * D_ + h * HD_);
    float4 kreg[HD_ / 4];
    #pragma unroll
    for (int e4 = 0; e4 < HD_ / 4; e4++) kreg[e4] = kr4[e4];

    float* orow = attn + (size_t)bh * L_ * S_ + s;
    for (int l0 = 0; l0 < L_; l0 += 20) {
        float acc[20];
        #pragma unroll
        for (int i = 0; i < 20; i++) acc[i] = 0.0f;
        #pragma unroll
        for (int i = 0; i < 20; i++) {
            const float* qrow = &qs[(size_t)(l0 + i) * HD_];
            #pragma unroll
            for (int e4 = 0; e4 < HD_ / 4; e4++) {
                const float4 qq = *(const float4*)&qrow[e4 * 4];
                const float4 kk = kreg[e4];
                acc[i] = fmaf(qq.x, kk.x, acc[i]);
                acc[i] = fmaf(qq.y, kk.y, acc[i]);
                acc[i] = fmaf(qq.z, kk.z, acc[i]);
                acc[i] = fmaf(qq.w, kk.w, acc[i]);
            }
        }
        #pragma unroll
        for (int i = 0; i < 20; i++) orow[(size_t)(l0 + i) * S_] = acc[i];
    }
}

// ---------------- softmax in place + head-mean a_score ----------------
__global__ void softmax_mean(float* __restrict__ attn, float* __restrict__ ascore)
{
    __shared__ float sm[8];
    const int l = blockIdx.x, b = blockIdx.y;
    const int tid = threadIdx.x;
    float am[4] = {0.f, 0.f, 0.f, 0.f};
    for (int h = 0; h < H_; h++) {
        float* row = attn + (((size_t)(b * H_ + h)) * L_ + l) * S_;
        float v[4];
        float mx = -INFINITY;
        #pragma unroll
        for (int j = 0; j < 4; j++) { v[j] = row[tid + j * 256]; mx = fmaxf(mx, v[j]); }
        mx = blockMax256(mx, sm);
        float ssum = 0.0f;
        #pragma unroll
        for (int j = 0; j < 4; j++) { v[j] = expf(v[j] - mx); ssum += v[j]; }
        ssum = blockSum256(ssum, sm);
        const float inv = 1.0f / ssum;
        #pragma unroll
        for (int j = 0; j < 4; j++) {
            const float p = v[j] * inv;
            row[tid + j * 256] = p;
            am[j] += p * (1.0f / H_);
        }
    }
    float* ao = ascore + ((size_t)b * L_ + l) * S_;
    #pragma unroll
    for (int j = 0; j < 4; j++) ao[tid + j * 256] = am[j];
}

// ---------------- ao[b,l,h,:] = attn[b,h,l,:] @ v[b,:,h,:] ----------------
#define AV_ST 32
__global__ __launch_bounds__(256)
void attn_v(const float* __restrict__ attn, const float* __restrict__ v,
            float* __restrict__ ao)
{
    const int bh = blockIdx.x, b = bh >> 3, h = bh & 7;
    const float* A = attn + (size_t)bh * L_ * S_;
    const float* V = v + (size_t)b * S_ * D_ + h * HD_;
    __shared__ float As[AV_ST][113];
    __shared__ float Vs[AV_ST][HD_];
    const int tid = threadIdx.x;
    const int tx = tid & 15, ty = tid >> 4;
    float acc[7][6];
    #pragma unroll
    for (int i = 0; i < 7; i++)
        #pragma unroll
        for (int j = 0; j < 6; j++) acc[i][j] = 0.0f;

    for (int idx = tid; idx < AV_ST * 13; idx += 256)
        As[idx / 13][100 + idx % 13] = 0.0f;

    for (int s0 = 0; s0 < S_; s0 += AV_ST) {
        for (int idx = tid; idx < L_ * AV_ST; idx += 256) {
            const int m = idx / AV_ST, ss = idx - m * AV_ST;
            As[ss][m] = A[(size_t)m * S_ + s0 + ss];
        }
        for (int idx = tid; idx < AV_ST * HD_; idx += 256) {
            const int r = idx / HD_, c = idx - r * HD_;
            Vs[r][c] = V[(size_t)(s0 + r) * D_ + c];
        }
        __syncthreads();
        #pragma unroll 4
        for (int ss = 0; ss < AV_ST; ss++) {
            float ra[7], rb[6];
            #pragma unroll
            for (int i = 0; i < 7; i++) ra[i] = As[ss][ty + 16 * i];
            #pragma unroll
            for (int j = 0; j < 6; j++) rb[j] = Vs[ss][tx + 16 * j];
            #pragma unroll
            for (int i = 0; i < 7; i++)
                #pragma unroll
                for (int j = 0; j < 6; j++)
                    acc[i][j] = fmaf(ra[i], rb[j], acc[i][j]);
        }
        __syncthreads();
    }
    #pragma unroll
    for (int i = 0; i < 7; i++) {
        const int m = ty + 16 * i;
        if (m < L_) {
            float* orow = ao + ((size_t)b * L_ + m) * D_ + h * HD_;
            #pragma unroll
            for (int j = 0; j < 6; j++) orow[tx + 16 * j] = acc[i][j];
        }
    }
}

// ---------------- GroupFC batch-independent term + bias ----------------
__global__ void yterm_kernel(const float* __restrict__ y, const float* __restrict__ dp,
                             const float* __restrict__ dbias, float* __restrict__ yt)
{
    const int l = blockIdx.x;
    const int w = threadIdx.x >> 5, lane = threadIdx.x & 31;
    const float* dpl = dp + (size_t)l * (2 * D_) * DF_ + (size_t)D_ * DF_ + w;
    const float* yr = y + (size_t)l * D_;
    float acc = 0.0f;
    for (int d = lane; d < D_; d += 32) acc = fmaf(yr[d], dpl[(size_t)d * DF_], acc);
    #pragma unroll
    for (int o = 16; o > 0; o >>= 1) acc += __shfl_xor_sync(0xffffffffu, acc, o);
    if (lane == 0) yt[l * DF_ + w] = acc + dbias[l * DF_ + w];
}

// ---------------- logits ----------------
__global__ void logits_kernel(const float* __restrict__ hh, const float* __restrict__ dp,
                              const float* __restrict__ yt, float* __restrict__ out)
{
    const int l = blockIdx.x, b = blockIdx.y;
    const int w = threadIdx.x >> 5, lane = threadIdx.x & 31;
    __shared__ float hs[D_];
    for (int i = threadIdx.x; i < D_; i += 320) hs[i] = hh[((size_t)b * L_ + l) * D_ + i];
    __syncthreads();
    const float* dpl = dp + (size_t)l * (2 * D_) * DF_ + w;
    float acc = 0.0f;
    for (int d = lane; d < D_; d += 32) acc = fmaf(hs[d], dpl[(size_t)d * DF_], acc);
    #pragma unroll
    for (int o = 16; o > 0; o >>= 1) acc += __shfl_xor_sync(0xffffffffu, acc, o);
    if (lane == 0) out[(size_t)b * C_ + l * DF_ + w] = acc + yt[l * DF_ + w];
}

// ---------------- host launch ----------------
extern "C" void kernel_launch(void* const* d_in, const int* in_sizes, int n_in,
                              void* d_out, int out_size)
{
    const float* x       = (const float*)d_in[0];
    const float* y       = (const float*)d_in[1];
    const float* embed_W = (const float*)d_in[2];
    const float* embed_b = (const float*)d_in[3];
    const float* Wq      = (const float*)d_in[4];
    const float* Wk      = (const float*)d_in[5];
    const float* Wv      = (const float*)d_in[6];
    const float* bq      = (const float*)d_in[7];
    const float* bk      = (const float*)d_in[8];
    const float* bv      = (const float*)d_in[9];
    const float* Wo      = (const float*)d_in[10];
    const float* bo      = (const float*)d_in[11];
    const float* ln1_g   = (const float*)d_in[12];
    const float* ln1_b   = (const float*)d_in[13];
    const float* ln2_g   = (const float*)d_in[14];
    const float* ln2_b   = (const float*)d_in[15];
    const float* ln3_g   = (const float*)d_in[16];
    const float* ln3_b   = (const float*)d_in[17];
    const float* W1      = (const float*)d_in[18];
    const float* b1      = (const float*)d_in[19];
    const float* W2      = (const float*)d_in[20];
    const float* b2      = (const float*)d_in[21];
    const float* dp      = (const float*)d_in[22];
    const float* dbias   = (const float*)d_in[23];
    float* out = (float*)d_out;

    float *pt, *pq, *pmem, *pk, *pv, *pattn, *pao, *px2, *pt2, *pf1, *px3, *ph, *pyt, *pdump;
    cudaGetSymbolAddress((void**)&pt,    g_t);
    cudaGetSymbolAddress((void**)&pq,    g_q);
    cudaGetSymbolAddress((void**)&pmem,  g_mem);
    cudaGetSymbolAddress((void**)&pk,    g_k);
    cudaGetSymbolAddress((void**)&pv,    g_v);
    cudaGetSymbolAddress((void**)&pattn, g_attn);
    cudaGetSymbolAddress((void**)&pao,   g_ao);
    cudaGetSymbolAddress((void**)&px2,   g_x2);
    cudaGetSymbolAddress((void**)&pt2,   g_t2);
    cudaGetSymbolAddress((void**)&pf1,   g_f1);
    cudaGetSymbolAddress((void**)&px3,   g_x3);
    cudaGetSymbolAddress((void**)&ph,    g_h);
    cudaGetSymbolAddress((void**)&pyt,   g_yt);
    cudaGetSymbolAddress((void**)&pdump, g_ascdump);

    cudaFuncSetAttribute(gemm_hmma<true, 0>,  cudaFuncAttributeMaxDynamicSharedMemorySize, GM_SMEM);
    cudaFuncSetAttribute(gemm_hmma<false, 0>, cudaFuncAttributeMaxDynamicSharedMemorySize, GM_SMEM);
    cudaFuncSetAttribute(gemm_hmma<false, 1>, cudaFuncAttributeMaxDynamicSharedMemorySize, GM_SMEM);
    cudaFuncSetAttribute(gemm_hmma<false, 2>, cudaFuncAttributeMaxDynamicSharedMemorySize, GM_SMEM);

    float* asc = (out_size >= B_ * C_ + B_ * L_ * S_) ? (out + B_ * C_) : pdump;

    // batch-independent preamble
    ln_rows<<<L_, 256>>>(y, ln1_g, ln1_b, pt, 2.0f);                       // t = LN(2y)
    qproj<<<dim3(L_, D_ / 128), 128>>>(pt, Wq, bq, pq);                    // q (scaled)
    yterm_kernel<<<L_, 320>>>(y, dp, dbias, pyt);

    // mem = relu(x @ We^T + eb)
    gemm_hmma<true, 0><<<dim3(D_ / 128, BS_ / 128), 256, GM_SMEM>>>(
        x, embed_W, embed_b, nullptr, pmem, BS_, D_, F0_, 0);
    // k, v
    gemm_hmma<false, 0><<<dim3(D_ / 128, BS_ / 128), 256, GM_SMEM>>>(
        pmem, Wk, bk, nullptr, pk, BS_, D_, D_, 0);
    gemm_hmma<false, 0><<<dim3(D_ / 128, BS_ / 128), 256, GM_SMEM>>>(
        pmem, Wv, bv, nullptr, pv, BS_, D_, D_, 0);

    // attention
    scores_kernel<<<dim3(S_ / 128, B_ * H_), 128>>>(pq, pk, pattn);
    softmax_mean<<<dim3(L_, B_), 256>>>(pattn, asc);
    attn_v<<<B_ * H_, 256>>>(pattn, pv, pao);

    // out-proj + residual t[l], then LN2
    gemm_hmma<false, 2><<<dim3(D_ / 128, BL_ / 128), 256, GM_SMEM>>>(
        pao, Wo, bo, pt, px2, BL_, D_, D_, L_);
    ln_rows<<<BL_, 256>>>(px2, ln2_g, ln2_b, pt2, 1.0f);

    // FFN + residual, LN3
    gemm_hmma<true, 0><<<dim3(D_ / 128, BL_ / 128), 256, GM_SMEM>>>(
        pt2, W1, b1, nullptr, pf1, BL_, D_, D_, 0);
    gemm_hmma<false, 1><<<dim3(D_ / 128, BL_ / 128), 256, GM_SMEM>>>(
        pf1, W2, b2, pt2, px3, BL_, D_, D_, 0);
    ln_rows<<<BL_, 256>>>(px3, ln3_g, ln3_b, ph, 1.0f);

    // GroupFC logits
    logits_kernel<<<dim3(L_, B_), 320>>>(ph, dp, pyt, out);
}

// round 8
// speedup vs baseline: 2.3801x; 1.1175x over previous
#include <cuda_runtime.h>
#include <cuda_fp16.h>
#include <math.h>
#include <stdint.h>

#define B_  32
#define S_  1024
#define F0_ 2048
#define D_  768
#define L_  100
#define H_  8
#define HD_ 96
#define DF_ 10
#define C_  1000
#define BL_ (B_*L_)   // 3200
#define BS_ (B_*S_)   // 32768
#define NKV_ 1536

// ---------------- scratch (static __device__, allocation-free) ----------------
static __device__ __align__(128) float g_t  [L_*D_];
static __device__ __align__(128) float g_q  [L_*D_];
static __device__ __align__(128) float g_attn[(size_t)B_*H_*L_*S_];
static __device__ __align__(128) float g_kv [(size_t)BS_*NKV_];   // k | v, pitch 1536
static __device__ __align__(128) float g_x2 [(size_t)BL_*D_];
static __device__ __align__(128) float g_t2 [(size_t)BL_*D_];
static __device__ __align__(128) float g_x3 [(size_t)BL_*D_];
static __device__ __align__(128) float g_h  [(size_t)BL_*D_];
static __device__ __align__(128) float g_yt [C_];
static __device__ __align__(128) float g_bkv[NKV_];
static __device__ __align__(128) float g_ascdump[(size_t)B_*L_*S_];

// fp16 operand planes
static __device__ __align__(128) __half g_xh [(size_t)BS_*F0_];
static __device__ __align__(128) __half g_xl [(size_t)BS_*F0_];
static __device__ __align__(128) __half g_memh[(size_t)BS_*D_];
static __device__ __align__(128) __half g_meml[(size_t)BS_*D_];
static __device__ __align__(128) __half g_aoh[(size_t)BL_*D_];
static __device__ __align__(128) __half g_aol[(size_t)BL_*D_];
static __device__ __align__(128) __half g_t2h[(size_t)BL_*D_];
static __device__ __align__(128) __half g_t2l[(size_t)BL_*D_];
static __device__ __align__(128) __half g_f1h[(size_t)BL_*D_];
static __device__ __align__(128) __half g_f1l[(size_t)BL_*D_];
static __device__ __align__(128) __half g_wemb[(size_t)D_*F0_];
static __device__ __align__(128) __half g_wkv [(size_t)NKV_*D_];
static __device__ __align__(128) __half g_wo  [(size_t)D_*D_];
static __device__ __align__(128) __half g_w1  [(size_t)D_*D_];
static __device__ __align__(128) __half g_w2  [(size_t)D_*D_];

// ============================================================================
// PTX helpers (sm_80-era baseline; safe on non-'a' compute_103 PTX target)
// ============================================================================
__device__ __forceinline__ uint32_t smem_u32(const void* p) {
    uint32_t a;
    asm("{ .reg .u64 t; cvta.to.shared.u64 t, %1; cvt.u32.u64 %0, t; }" : "=r"(a) : "l"(p));
    return a;
}
#define LDSM4(r, addr)                                                            \
    asm volatile("ldmatrix.sync.aligned.m8n8.x4.shared.b16 {%0,%1,%2,%3}, [%4];"  \
        : "=r"((r)[0]), "=r"((r)[1]), "=r"((r)[2]), "=r"((r)[3]) : "r"(addr))
#define MMAF16(c, a, b0, b1)                                                      \
    asm volatile("mma.sync.aligned.m16n8k16.row.col.f32.f16.f16.f32 "             \
        "{%0,%1,%2,%3}, {%4,%5,%6,%7}, {%8,%9}, {%0,%1,%2,%3};"                   \
        : "+f"((c)[0]), "+f"((c)[1]), "+f"((c)[2]), "+f"((c)[3])                  \
        : "r"((a)[0]), "r"((a)[1]), "r"((a)[2]), "r"((a)[3]), "r"(b0), "r"(b1))
#define CP16(dst, src)                                                            \
    asm volatile("cp.async.cg.shared.global [%0], [%1], 16;" :: "r"(dst), "l"(src))
#define CP_COMMIT() asm volatile("cp.async.commit_group;" ::: "memory")
#define CP_WAIT(n)  asm volatile("cp.async.wait_group %0;" :: "n"(n) : "memory")

// SW128-style swizzle for 64B logical rows packed 2-per-128B line.
// r: row 0..127, kb: 16B chunk 0..3 within the row.
__device__ __forceinline__ uint32_t swz_addr(uint32_t base, int r, int kb) {
    uint32_t line = (uint32_t)r >> 1;
    uint32_t slot = ((((uint32_t)r & 1u) << 2) | (uint32_t)kb) ^ (line & 7u);
    return base + line * 128u + slot * 16u;
}

// ============================================================================
// 2-pass fp16 HMMA GEMM:  C = act((Ah+Al) * B^T + bias [+ res])
// Ah/Al: (M,K) fp16 planes; Bw: (N,K) fp16. M%128==0, N%128==0, K%32==0.
// RES: 0 none, 1 full fp32 (M,N), 2 broadcast fp32 Res[m % resMod].
// Outputs: C fp32 (nullable), Chi/Clo fp16 split (nullable).
// 128 threads (2x2 warps, 64x64 warp tiles), 4-stage cp.async, 2 CTAs/SM.
// ============================================================================
#define NSTG 4
#define STG_BYTES 24576u            // Ah 8K | Al 8K | B 8K
#define GM_SMEM (NSTG * STG_BYTES)  // 98304

__device__ __forceinline__ void load_stage(uint32_t sbase,
    const __half* __restrict__ Ah, const __half* __restrict__ Al,
    const __half* __restrict__ Bw, int bm, int bn, int K, int k0, int row)
{
    const __half* pa = Ah + (size_t)(bm + row) * K + k0;
    const __half* pl = Al + (size_t)(bm + row) * K + k0;
    const __half* pb = Bw + (size_t)(bn + row) * K + k0;
    #pragma unroll
    for (int kb = 0; kb < 4; kb++) {
        CP16(swz_addr(sbase, row, kb),           pa + kb * 8);
        CP16(swz_addr(sbase + 8192u, row, kb),   pl + kb * 8);
        CP16(swz_addr(sbase + 16384u, row, kb),  pb + kb * 8);
    }
    CP_COMMIT();
}

template<bool RELU, int RES>
__global__ void __launch_bounds__(128, 2)
gemm16(const __half* __restrict__ Ah, const __half* __restrict__ Al,
       const __half* __restrict__ Bw, const float* __restrict__ bias,
       const float* __restrict__ Res, float* __restrict__ C,
       __half* __restrict__ Chi, __half* __restrict__ Clo,
       int M, int N, int K, int resMod)
{
    extern __shared__ char smem[];
    const uint32_t sb = smem_u32(smem);
    const int tid = threadIdx.x, lane = tid & 31, wid = tid >> 5;
    const int wm = wid & 1, wn = wid >> 1;
    const int bm = blockIdx.y * 128, bn = blockIdx.x * 128;
    const int nc = K >> 5;

    float c[4][8][4];
    #pragma unroll
    for (int mt = 0; mt < 4; mt++)
        #pragma unroll
        for (int nt = 0; nt < 8; nt++)
            #pragma unroll
            for (int q = 0; q < 4; q++) c[mt][nt][q] = 0.0f;

    // precomputed per-lane ldmatrix offsets (relative to stage base)
    uint32_t offA[4][2], offB[2][2][2];
    {
        const int aR = lane & 15, aKb = lane >> 4;
        const int bR = (lane & 7) | ((lane >> 4) << 3);
        const int bKb = (lane >> 3) & 1;
        #pragma unroll
        for (int mt = 0; mt < 4; mt++)
            #pragma unroll
            for (int ks = 0; ks < 2; ks++)
                offA[mt][ks] = swz_addr(0, wm * 64 + mt * 16 + aR, ks * 2 + aKb);
        #pragma unroll
        for (int nh = 0; nh < 2; nh++)
            #pragma unroll
            for (int p = 0; p < 2; p++)
                #pragma unroll
                for (int ks = 0; ks < 2; ks++)
                    offB[nh][p][ks] = 16384u +
                        swz_addr(0, wn * 64 + nh * 32 + p * 16 + bR, ks * 2 + bKb);
    }

    // prologue: stages 0..2
    #pragma unroll
    for (int s = 0; s < 3; s++)
        load_stage(sb + s * STG_BYTES, Ah, Al, Bw, bm, bn, K, s * 32, tid);

    for (int i = 0; i < nc; i++) {
        CP_WAIT(2);
        __syncthreads();
        if (i + 3 < nc)
            load_stage(sb + (uint32_t)((i + 3) & 3) * STG_BYTES, Ah, Al, Bw,
                       bm, bn, K, (i + 3) * 32, tid);
        const uint32_t st = sb + (uint32_t)(i & 3) * STG_BYTES;
        #pragma unroll
        for (int ks = 0; ks < 2; ks++) {
            uint32_t aH[4][4], aL[4][4];
            #pragma unroll
            for (int mt = 0; mt < 4; mt++) {
                LDSM4(aH[mt], st + offA[mt][ks]);
                LDSM4(aL[mt], st + 8192u + offA[mt][ks]);
            }
            #pragma unroll
            for (int nh = 0; nh < 2; nh++) {
                uint32_t bf[2][4];
                #pragma unroll
                for (int p = 0; p < 2; p++) LDSM4(bf[p], st + offB[nh][p][ks]);
                #pragma unroll
                for (int mt = 0; mt < 4; mt++)
                    #pragma unroll
                    for (int nt = 0; nt < 4; nt++) {
                        const uint32_t b0 = bf[nt >> 1][(nt & 1) * 2];
                        const uint32_t b1 = bf[nt >> 1][(nt & 1) * 2 + 1];
                        MMAF16(c[mt][nh * 4 + nt], aH[mt], b0, b1);
                        MMAF16(c[mt][nh * 4 + nt], aL[mt], b0, b1);
                    }
            }
        }
    }

    // epilogue
    #pragma unroll
    for (int mt = 0; mt < 4; mt++) {
        #pragma unroll
        for (int hh = 0; hh < 2; hh++) {
            const int m = bm + wm * 64 + mt * 16 + (lane >> 2) + hh * 8;
            const float* resRow = (RES == 1) ? (Res + (size_t)m * N)
                                : (RES == 2) ? (Res + (size_t)(m % resMod) * N)
                                : nullptr;
            #pragma unroll
            for (int nt = 0; nt < 8; nt++) {
                const int n = bn + wn * 64 + nt * 8 + (lane & 3) * 2;
                float vx = c[mt][nt][hh * 2 + 0] + bias[n + 0];
                float vy = c[mt][nt][hh * 2 + 1] + bias[n + 1];
                if (RES != 0) { vx += resRow[n + 0]; vy += resRow[n + 1]; }
                if (RELU) { vx = fmaxf(vx, 0.f); vy = fmaxf(vy, 0.f); }
                if (C) *(float2*)(C + (size_t)m * N + n) = make_float2(vx, vy);
                if (Chi) {
                    __half hx = __float2half_rn(vx), hy = __float2half_rn(vy);
                    __half lx = __float2half_rn(vx - __half2float(hx));
                    __half ly = __float2half_rn(vy - __half2float(hy));
                    *(__half2*)(Chi + (size_t)m * N + n) = __halves2half2(hx, hy);
                    *(__half2*)(Clo + (size_t)m * N + n) = __halves2half2(lx, ly);
                }
            }
        }
    }
}

// ---------------- converters ----------------
__global__ void cvt_split16(const float* __restrict__ in, __half* __restrict__ hi,
                            __half* __restrict__ lo, int n4)
{
    int i = blockIdx.x * 256 + threadIdx.x;
    if (i >= n4) return;
    float4 f = ((const float4*)in)[i];
    __half2 h0 = __floats2half2_rn(f.x, f.y);
    __half2 h1 = __floats2half2_rn(f.z, f.w);
    float2 r0 = __half22float2(h0), r1 = __half22float2(h1);
    __half2 l0 = __floats2half2_rn(f.x - r0.x, f.y - r0.y);
    __half2 l1 = __floats2half2_rn(f.z - r1.x, f.w - r1.y);
    ((__half2*)hi)[i * 2 + 0] = h0; ((__half2*)hi)[i * 2 + 1] = h1;
    ((__half2*)lo)[i * 2 + 0] = l0; ((__half2*)lo)[i * 2 + 1] = l1;
}
__global__ void cvt_h16(const float* __restrict__ in, __half* __restrict__ out, int n4)
{
    int i = blockIdx.x * 256 + threadIdx.x;
    if (i >= n4) return;
    float4 f = ((const float4*)in)[i];
    ((__half2*)out)[i * 2 + 0] = __floats2half2_rn(f.x, f.y);
    ((__half2*)out)[i * 2 + 1] = __floats2half2_rn(f.z, f.w);
}
__global__ void concat_bias(const float* __restrict__ bk, const float* __restrict__ bv,
                            float* __restrict__ bkv)
{
    int i = blockIdx.x * 256 + threadIdx.x;
    if (i < D_) bkv[i] = bk[i];
    else if (i < NKV_) bkv[i] = bv[i - D_];
}

// ---------------- block reductions (256 threads = 8 warps) ----------------
__device__ __forceinline__ float blockSum256(float v, float* sm) {
    #pragma unroll
    for (int o = 16; o > 0; o >>= 1) v += __shfl_xor_sync(0xffffffffu, v, o);
    const int w = threadIdx.x >> 5, lane = threadIdx.x & 31;
    if (lane == 0) sm[w] = v;
    __syncthreads();
    float r = (lane < 8) ? sm[lane] : 0.0f;
    #pragma unroll
    for (int o = 4; o > 0; o >>= 1) r += __shfl_xor_sync(0xffffffffu, r, o);
    r = __shfl_sync(0xffffffffu, r, 0);
    __syncthreads();
    return r;
}
__device__ __forceinline__ float blockMax256(float v, float* sm) {
    #pragma unroll
    for (int o = 16; o > 0; o >>= 1) v = fmaxf(v, __shfl_xor_sync(0xffffffffu, v, o));
    const int w = threadIdx.x >> 5, lane = threadIdx.x & 31;
    if (lane == 0) sm[w] = v;
    __syncthreads();
    float r = (lane < 8) ? sm[lane] : -INFINITY;
    #pragma unroll
    for (int o = 4; o > 0; o >>= 1) r = fmaxf(r, __shfl_xor_sync(0xffffffffu, r, o));
    r = __shfl_sync(0xffffffffu, r, 0);
    __syncthreads();
    return r;
}

// ---------------- row LayerNorm; optional fp16 hi/lo split output ----------------
__global__ void ln_rows(const float* __restrict__ X, const float* __restrict__ gg,
                        const float* __restrict__ bb, float* __restrict__ O, float alpha,
                        __half* __restrict__ Oh, __half* __restrict__ Ol)
{
    __shared__ float sm[8];
    const int row = blockIdx.x;
    const float* x = X + (size_t)row * D_;
    float v[3];
    float s = 0.0f, sq = 0.0f;
    #pragma unroll
    for (int j = 0; j < 3; j++) {
        v[j] = alpha * x[threadIdx.x + j * 256];
        s += v[j]; sq += v[j] * v[j];
    }
    s  = blockSum256(s, sm);
    sq = blockSum256(sq, sm);
    const float mean = s * (1.0f / D_);
    const float var  = sq * (1.0f / D_) - mean * mean;
    const float inv  = rsqrtf(var + 1e-5f);
    float* o = O + (size_t)row * D_;
    #pragma unroll
    for (int j = 0; j < 3; j++) {
        const int i = threadIdx.x + j * 256;
        const float ov = (v[j] - mean) * inv * gg[i] + bb[i];
        o[i] = ov;
        if (Oh) {
            __half hx = __float2half_rn(ov);
            Oh[(size_t)row * D_ + i] = hx;
            Ol[(size_t)row * D_ + i] = __float2half_rn(ov - __half2float(hx));
        }
    }
}

// ---------------- q projection (L=100 rows), folds 1/sqrt(hd) ----------------
__global__ void qproj(const float* __restrict__ t, const float* __restrict__ Wq,
                      const float* __restrict__ bq, float* __restrict__ q)
{
    const int l = blockIdx.x;
    const int e = blockIdx.y * 128 + threadIdx.x;
    __shared__ float ts[D_];
    for (int i = threadIdx.x; i < D_; i += 128) ts[i] = t[(size_t)l * D_ + i];
    __syncthreads();
    const float* w = Wq + (size_t)e * D_;
    float acc = 0.0f;
    #pragma unroll 8
    for (int d = 0; d < D_; d++) acc = fmaf(ts[d], w[d], acc);
    q[(size_t)l * D_ + e] = (acc + bq[e]) * 0.10206207261596575f;  // 1/sqrt(96)
}

// ---------------- scores: attn[b,h,l,s] = q_h[l,:] . k[b,s,h,:] (kv pitch 1536) ----
__global__ __launch_bounds__(128)
void scores_kernel(const float* __restrict__ q, const float* __restrict__ kv,
                   float* __restrict__ attn)
{
    const int bh = blockIdx.y, b = bh >> 3, h = bh & 7;
    const int s = blockIdx.x * 128 + threadIdx.x;
    __shared__ float qs[L_ * HD_];
    for (int idx = threadIdx.x; idx < L_ * HD_; idx += 128) {
        const int l = idx / HD_, e = idx - l * HD_;
        qs[idx] = q[(size_t)l * D_ + h * HD_ + e];
    }
    __syncthreads();
    const float4* kr4 = (const float4*)(kv + ((size_t)b * S_ + s) * NKV_ + h * HD_);
    float4 kreg[HD_ / 4];
    #pragma unroll
    for (int e4 = 0; e4 < HD_ / 4; e4++) kreg[e4] = kr4[e4];

    float* orow = attn + (size_t)bh * L_ * S_ + s;
    for (int l0 = 0; l0 < L_; l0 += 20) {
        float acc[20];
        #pragma unroll
        for (int i = 0; i < 20; i++) acc[i] = 0.0f;
        #pragma unroll
        for (int i = 0; i < 20; i++) {
            const float* qrow = &qs[(size_t)(l0 + i) * HD_];
            #pragma unroll
            for (int e4 = 0; e4 < HD_ / 4; e4++) {
                const float4 qq = *(const float4*)&qrow[e4 * 4];
                const float4 kk = kreg[e4];
                acc[i] = fmaf(qq.x, kk.x, acc[i]);
                acc[i] = fmaf(qq.y, kk.y, acc[i]);
                acc[i] = fmaf(qq.z, kk.z, acc[i]);
                acc[i] = fmaf(qq.w, kk.w, acc[i]);
            }
        }
        #pragma unroll
        for (int i = 0; i < 20; i++) orow[(size_t)(l0 + i) * S_] = acc[i];
    }
}

// ---------------- softmax in place + head-mean a_score ----------------
__global__ void softmax_mean(float* __restrict__ attn, float* __restrict__ ascore)
{
    __shared__ float sm[8];
    const int l = blockIdx.x, b = blockIdx.y;
    const int tid = threadIdx.x;
    float am[4] = {0.f, 0.f, 0.f, 0.f};
    for (int h = 0; h < H_; h++) {
        float* row = attn + (((size_t)(b * H_ + h)) * L_ + l) * S_;
        float v[4];
        float mx = -INFINITY;
        #pragma unroll
        for (int j = 0; j < 4; j++) { v[j] = row[tid + j * 256]; mx = fmaxf(mx, v[j]); }
        mx = blockMax256(mx, sm);
        float ssum = 0.0f;
        #pragma unroll
        for (int j = 0; j < 4; j++) { v[j] = expf(v[j] - mx); ssum += v[j]; }
        ssum = blockSum256(ssum, sm);
        const float inv = 1.0f / ssum;
        #pragma unroll
        for (int j = 0; j < 4; j++) {
            const float p = v[j] * inv;
            row[tid + j * 256] = p;
            am[j] += p * (1.0f / H_);
        }
    }
    float* ao = ascore + ((size_t)b * L_ + l) * S_;
    #pragma unroll
    for (int j = 0; j < 4; j++) ao[tid + j * 256] = am[j];
}

// ---------------- ao[b,l,h,:] = attn[b,h,l,:] @ v[b,:,h,:]; fp16 split output ----
#define AV_ST 32
__global__ __launch_bounds__(256)
void attn_v(const float* __restrict__ attn, const float* __restrict__ kv,
            __half* __restrict__ aoh, __half* __restrict__ aol)
{
    const int bh = blockIdx.x, b = bh >> 3, h = bh & 7;
    const float* A = attn + (size_t)bh * L_ * S_;
    const float* V = kv + (size_t)b * S_ * NKV_ + D_ + h * HD_;
    __shared__ float As[AV_ST][113];
    __shared__ float Vs[AV_ST][HD_];
    const int tid = threadIdx.x;
    const int tx = tid & 15, ty = tid >> 4;
    float acc[7][6];
    #pragma unroll
    for (int i = 0; i < 7; i++)
        #pragma unroll
        for (int j = 0; j < 6; j++) acc[i][j] = 0.0f;

    for (int idx = tid; idx < AV_ST * 13; idx += 256)
        As[idx / 13][100 + idx % 13] = 0.0f;

    for (int s0 = 0; s0 < S_; s0 += AV_ST) {
        for (int idx = tid; idx < L_ * AV_ST; idx += 256) {
            const int m = idx / AV_ST, ss = idx - m * AV_ST;
            As[ss][m] = A[(size_t)m * S_ + s0 + ss];
        }
        for (int idx = tid; idx < AV_ST * HD_; idx += 256) {
            const int r = idx / HD_, cc = idx - r * HD_;
            Vs[r][cc] = V[(size_t)(s0 + r) * NKV_ + cc];
        }
        __syncthreads();
        #pragma unroll 4
        for (int ss = 0; ss < AV_ST; ss++) {
            float ra[7], rb[6];
            #pragma unroll
            for (int i = 0; i < 7; i++) ra[i] = As[ss][ty + 16 * i];
            #pragma unroll
            for (int j = 0; j < 6; j++) rb[j] = Vs[ss][tx + 16 * j];
            #pragma unroll
            for (int i = 0; i < 7; i++)
                #pragma unroll
                for (int j = 0; j < 6; j++)
                    acc[i][j] = fmaf(ra[i], rb[j], acc[i][j]);
        }
        __syncthreads();
    }
    #pragma unroll
    for (int i = 0; i < 7; i++) {
        const int m = ty + 16 * i;
        if (m < L_) {
            const size_t base = ((size_t)b * L_ + m) * D_ + h * HD_;
            #pragma unroll
            for (int j = 0; j < 6; j++) {
                const float v = acc[i][j];
                const __half hx = __float2half_rn(v);
                aoh[base + tx + 16 * j] = hx;
                aol[base + tx + 16 * j] = __float2half_rn(v - __half2float(hx));
            }
        }
    }
}

// ---------------- GroupFC batch-independent term + bias ----------------
__global__ void yterm_kernel(const float* __restrict__ y, const float* __restrict__ dp,
                             const float* __restrict__ dbias, float* __restrict__ yt)
{
    const int l = blockIdx.x;
    const int w = threadIdx.x >> 5, lane = threadIdx.x & 31;
    const float* dpl = dp + (size_t)l * (2 * D_) * DF_ + (size_t)D_ * DF_ + w;
    const float* yr = y + (size_t)l * D_;
    float acc = 0.0f;
    for (int d = lane; d < D_; d += 32) acc = fmaf(yr[d], dpl[(size_t)d * DF_], acc);
    #pragma unroll
    for (int o = 16; o > 0; o >>= 1) acc += __shfl_xor_sync(0xffffffffu, acc, o);
    if (lane == 0) yt[l * DF_ + w] = acc + dbias[l * DF_ + w];
}

// ---------------- logits ----------------
__global__ void logits_kernel(const float* __restrict__ hh, const float* __restrict__ dp,
                              const float* __restrict__ yt, float* __restrict__ out)
{
    const int l = blockIdx.x, b = blockIdx.y;
    const int w = threadIdx.x >> 5, lane = threadIdx.x & 31;
    __shared__ float hs[D_];
    for (int i = threadIdx.x; i < D_; i += 320) hs[i] = hh[((size_t)b * L_ + l) * D_ + i];
    __syncthreads();
    const float* dpl = dp + (size_t)l * (2 * D_) * DF_ + w;
    float acc = 0.0f;
    for (int d = lane; d < D_; d += 32) acc = fmaf(hs[d], dpl[(size_t)d * DF_], acc);
    #pragma unroll
    for (int o = 16; o > 0; o >>= 1) acc += __shfl_xor_sync(0xffffffffu, acc, o);
    if (lane == 0) out[(size_t)b * C_ + l * DF_ + w] = acc + yt[l * DF_ + w];
}

// ---------------- host launch ----------------
extern "C" void kernel_launch(void* const* d_in, const int* in_sizes, int n_in,
                              void* d_out, int out_size)
{
    const float* x       = (const float*)d_in[0];
    const float* y       = (const float*)d_in[1];
    const float* embed_W = (const float*)d_in[2];
    const float* embed_b = (const float*)d_in[3];
    const float* Wq      = (const float*)d_in[4];
    const float* Wk      = (const float*)d_in[5];
    const float* Wv      = (const float*)d_in[6];
    const float* bq      = (const float*)d_in[7];
    const float* bk      = (const float*)d_in[8];
    const float* bv      = (const float*)d_in[9];
    const float* Wo      = (const float*)d_in[10];
    const float* bo      = (const float*)d_in[11];
    const float* ln1_g   = (const float*)d_in[12];
    const float* ln1_b   = (const float*)d_in[13];
    const float* ln2_g   = (const float*)d_in[14];
    const float* ln2_b   = (const float*)d_in[15];
    const float* ln3_g   = (const float*)d_in[16];
    const float* ln3_b   = (const float*)d_in[17];
    const float* W1      = (const float*)d_in[18];
    const float* b1      = (const float*)d_in[19];
    const float* W2      = (const float*)d_in[20];
    const float* b2      = (const float*)d_in[21];
    const float* dp      = (const float*)d_in[22];
    const float* dbias   = (const float*)d_in[23];
    float* out = (float*)d_out;

    float *pt, *pq, *pattn, *pkv, *px2, *pt2, *px3, *ph, *pyt, *pbkv, *pdump;
    __half *pxh, *pxl, *pmemh, *pmeml, *paoh, *paol, *pt2h, *pt2l, *pf1h, *pf1l;
    __half *pwemb, *pwkv, *pwo, *pw1, *pw2;
    cudaGetSymbolAddress((void**)&pt,    g_t);
    cudaGetSymbolAddress((void**)&pq,    g_q);
    cudaGetSymbolAddress((void**)&pattn, g_attn);
    cudaGetSymbolAddress((void**)&pkv,   g_kv);
    cudaGetSymbolAddress((void**)&px2,   g_x2);
    cudaGetSymbolAddress((void**)&pt2,   g_t2);
    cudaGetSymbolAddress((void**)&px3,   g_x3);
    cudaGetSymbolAddress((void**)&ph,    g_h);
    cudaGetSymbolAddress((void**)&pyt,   g_yt);
    cudaGetSymbolAddress((void**)&pbkv,  g_bkv);
    cudaGetSymbolAddress((void**)&pdump, g_ascdump);
    cudaGetSymbolAddress((void**)&pxh,   g_xh);
    cudaGetSymbolAddress((void**)&pxl,   g_xl);
    cudaGetSymbolAddress((void**)&pmemh, g_memh);
    cudaGetSymbolAddress((void**)&pmeml, g_meml);
    cudaGetSymbolAddress((void**)&paoh,  g_aoh);
    cudaGetSymbolAddress((void**)&paol,  g_aol);
    cudaGetSymbolAddress((void**)&pt2h,  g_t2h);
    cudaGetSymbolAddress((void**)&pt2l,  g_t2l);
    cudaGetSymbolAddress((void**)&pf1h,  g_f1h);
    cudaGetSymbolAddress((void**)&pf1l,  g_f1l);
    cudaGetSymbolAddress((void**)&pwemb, g_wemb);
    cudaGetSymbolAddress((void**)&pwkv,  g_wkv);
    cudaGetSymbolAddress((void**)&pwo,   g_wo);
    cudaGetSymbolAddress((void**)&pw1,   g_w1);
    cudaGetSymbolAddress((void**)&pw2,   g_w2);

    cudaFuncSetAttribute(gemm16<true, 0>,  cudaFuncAttributeMaxDynamicSharedMemorySize, GM_SMEM);
    cudaFuncSetAttribute(gemm16<false, 0>, cudaFuncAttributeMaxDynamicSharedMemorySize, GM_SMEM);
    cudaFuncSetAttribute(gemm16<false, 1>, cudaFuncAttributeMaxDynamicSharedMemorySize, GM_SMEM);
    cudaFuncSetAttribute(gemm16<false, 2>, cudaFuncAttributeMaxDynamicSharedMemorySize, GM_SMEM);

    float* asc = (out_size >= B_ * C_ + B_ * L_ * S_) ? (out + B_ * C_) : pdump;

    // ---- operand conversion ----
    cvt_split16<<<(BS_ * F0_ / 4 + 255) / 256, 256>>>(x, pxh, pxl, BS_ * F0_ / 4);
    cvt_h16<<<(D_ * F0_ / 4 + 255) / 256, 256>>>(embed_W, pwemb, D_ * F0_ / 4);
    cvt_h16<<<(D_ * D_ / 4 + 255) / 256, 256>>>(Wk, pwkv, D_ * D_ / 4);
    cvt_h16<<<(D_ * D_ / 4 + 255) / 256, 256>>>(Wv, pwkv + (size_t)D_ * D_, D_ * D_ / 4);
    cvt_h16<<<(D_ * D_ / 4 + 255) / 256, 256>>>(Wo, pwo, D_ * D_ / 4);
    cvt_h16<<<(D_ * D_ / 4 + 255) / 256, 256>>>(W1, pw1, D_ * D_ / 4);
    cvt_h16<<<(D_ * D_ / 4 + 255) / 256, 256>>>(W2, pw2, D_ * D_ / 4);
    concat_bias<<<(NKV_ + 255) / 256, 256>>>(bk, bv, pbkv);

    // ---- batch-independent preamble ----
    ln_rows<<<L_, 256>>>(y, ln1_g, ln1_b, pt, 2.0f, nullptr, nullptr);     // t = LN(2y)
    qproj<<<dim3(L_, D_ / 128), 128>>>(pt, Wq, bq, pq);
    yterm_kernel<<<L_, 320>>>(y, dp, dbias, pyt);

    // ---- mem = relu(x @ We^T + eb) -> fp16 hi/lo only ----
    gemm16<true, 0><<<dim3(D_ / 128, BS_ / 128), 128, GM_SMEM>>>(
        pxh, pxl, pwemb, embed_b, nullptr, nullptr, pmemh, pmeml, BS_, D_, F0_, 0);

    // ---- fused K|V GEMM -> fp32 kv (pitch 1536) ----
    gemm16<false, 0><<<dim3(NKV_ / 128, BS_ / 128), 128, GM_SMEM>>>(
        pmemh, pmeml, pwkv, pbkv, nullptr, pkv, nullptr, nullptr, BS_, NKV_, D_, 0);

    // ---- attention ----
    scores_kernel<<<dim3(S_ / 128, B_ * H_), 128>>>(pq, pkv, pattn);
    softmax_mean<<<dim3(L_, B_), 256>>>(pattn, asc);
    attn_v<<<B_ * H_, 256>>>(pattn, pkv, paoh, paol);

    // ---- out-proj + residual t[l], LN2 (fp32 + fp16 split) ----
    gemm16<false, 2><<<dim3(D_ / 128, BL_ / 128), 128, GM_SMEM>>>(
        paoh, paol, pwo, bo, pt, px2, nullptr, nullptr, BL_, D_, D_, L_);
    ln_rows<<<BL_, 256>>>(px2, ln2_g, ln2_b, pt2, 1.0f, pt2h, pt2l);

    // ---- FFN ----
    gemm16<true, 0><<<dim3(D_ / 128, BL_ / 128), 128, GM_SMEM>>>(
        pt2h, pt2l, pw1, b1, nullptr, nullptr, pf1h, pf1l, BL_, D_, D_, 0);
    gemm16<false, 1><<<dim3(D_ / 128, BL_ / 128), 128, GM_SMEM>>>(
        pf1h, pf1l, pw2, b2, pt2, px3, nullptr, nullptr, BL_, D_, D_, 0);
    ln_rows<<<BL_, 256>>>(px3, ln3_g, ln3_b, ph, 1.0f, nullptr, nullptr);

    // ---- GroupFC logits ----
    logits_kernel<<<dim3(L_, B_), 320>>>(ph, dp, pyt, out);
}

// round 9
// speedup vs baseline: 3.3929x; 1.4255x over previous
#include <cuda_runtime.h>
#include <cuda_fp16.h>
#include <math.h>
#include <stdint.h>

#define B_  32
#define S_  1024
#define F0_ 2048
#define D_  768
#define L_  100
#define H_  8
#define HD_ 96
#define DF_ 10
#define C_  1000
#define BL_ (B_*L_)   // 3200
#define BS_ (B_*S_)   // 32768
#define NKV_ 1536

// ---------------- scratch (static __device__, allocation-free) ----------------
static __device__ __align__(128) float g_t  [L_*D_];
static __device__ __align__(128) float g_q  [L_*D_];
static __device__ __align__(128) float g_attn[(size_t)B_*H_*L_*S_];
static __device__ __align__(128) float g_kv [(size_t)BS_*NKV_];   // k | v, pitch 1536
static __device__ __align__(128) float g_x2 [(size_t)BL_*D_];
static __device__ __align__(128) float g_t2 [(size_t)BL_*D_];
static __device__ __align__(128) float g_x3 [(size_t)BL_*D_];
static __device__ __align__(128) float g_h  [(size_t)BL_*D_];
static __device__ __align__(128) float g_yt [C_];
static __device__ __align__(128) float g_bkv[NKV_];
static __device__ __align__(128) float g_ascdump[(size_t)B_*L_*S_];

// fp16 operand planes (single plane per tensor — 1-pass HMMA)
static __device__ __align__(128) __half g_xh  [(size_t)BS_*F0_];
static __device__ __align__(128) __half g_memh[(size_t)BS_*D_];
static __device__ __align__(128) __half g_aoh [(size_t)BL_*D_];
static __device__ __align__(128) __half g_t2h [(size_t)BL_*D_];
static __device__ __align__(128) __half g_f1h [(size_t)BL_*D_];
static __device__ __align__(128) __half g_wemb[(size_t)D_*F0_];
static __device__ __align__(128) __half g_wkv [(size_t)NKV_*D_];
static __device__ __align__(128) __half g_wo  [(size_t)D_*D_];
static __device__ __align__(128) __half g_w1  [(size_t)D_*D_];
static __device__ __align__(128) __half g_w2  [(size_t)D_*D_];

// ============================================================================
// PTX helpers (sm_80-era baseline; safe on non-'a' compute_103 PTX target)
// ============================================================================
__device__ __forceinline__ uint32_t smem_u32(const void* p) {
    uint32_t a;
    asm("{ .reg .u64 t; cvta.to.shared.u64 t, %1; cvt.u32.u64 %0, t; }" : "=r"(a) : "l"(p));
    return a;
}
#define LDSM4(r, addr)                                                            \
    asm volatile("ldmatrix.sync.aligned.m8n8.x4.shared.b16 {%0,%1,%2,%3}, [%4];"  \
        : "=r"((r)[0]), "=r"((r)[1]), "=r"((r)[2]), "=r"((r)[3]) : "r"(addr))
#define MMAF16(c, a, b0, b1)                                                      \
    asm volatile("mma.sync.aligned.m16n8k16.row.col.f32.f16.f16.f32 "             \
        "{%0,%1,%2,%3}, {%4,%5,%6,%7}, {%8,%9}, {%0,%1,%2,%3};"                   \
        : "+f"((c)[0]), "+f"((c)[1]), "+f"((c)[2]), "+f"((c)[3])                  \
        : "r"((a)[0]), "r"((a)[1]), "r"((a)[2]), "r"((a)[3]), "r"(b0), "r"(b1))
#define CP16(dst, src)                                                            \
    asm volatile("cp.async.cg.shared.global [%0], [%1], 16;" :: "r"(dst), "l"(src))
#define CP_COMMIT() asm volatile("cp.async.commit_group;" ::: "memory")
#define CP_WAIT(n)  asm volatile("cp.async.wait_group %0;" :: "n"(n) : "memory")

// SW128-style swizzle for 64B logical rows packed 2-per-128B line.
__device__ __forceinline__ uint32_t swz_addr(uint32_t base, int r, int kb) {
    uint32_t line = (uint32_t)r >> 1;
    uint32_t slot = ((((uint32_t)r & 1u) << 2) | (uint32_t)kb) ^ (line & 7u);
    return base + line * 128u + slot * 16u;
}

// ============================================================================
// 1-pass fp16 HMMA GEMM:  C = act(A * B^T + bias [+ res])
// A: (M,K) fp16; Bw: (N,K) fp16. M%128==0, N%128==0, K%32==0.
// RES: 0 none, 1 full fp32 (M,N), 2 broadcast fp32 Res[m % resMod].
// Outputs: C fp32 (nullable), Chi fp16 (nullable).
// 128 threads (2x2 warps, 64x64 warp tiles), 4-stage cp.async, 2 CTAs/SM.
// ============================================================================
#define NSTG 4
#define STG_BYTES 16384u            // A 8K | B 8K
#define GM_SMEM (NSTG * STG_BYTES)  // 65536

__device__ __forceinline__ void load_stage(uint32_t sbase,
    const __half* __restrict__ Ah, const __half* __restrict__ Bw,
    int bm, int bn, int K, int k0, int row)
{
    const __half* pa = Ah + (size_t)(bm + row) * K + k0;
    const __half* pb = Bw + (size_t)(bn + row) * K + k0;
    #pragma unroll
    for (int kb = 0; kb < 4; kb++) {
        CP16(swz_addr(sbase, row, kb),          pa + kb * 8);
        CP16(swz_addr(sbase + 8192u, row, kb),  pb + kb * 8);
    }
    CP_COMMIT();
}

template<bool RELU, int RES>
__global__ void __launch_bounds__(128, 2)
gemm16(const __half* __restrict__ Ah, const __half* __restrict__ Bw,
       const float* __restrict__ bias, const float* __restrict__ Res,
       float* __restrict__ C, __half* __restrict__ Chi,
       int M, int N, int K, int resMod)
{
    extern __shared__ char smem[];
    const uint32_t sb = smem_u32(smem);
    const int tid = threadIdx.x, lane = tid & 31, wid = tid >> 5;
    const int wm = wid & 1, wn = wid >> 1;
    const int bm = blockIdx.y * 128, bn = blockIdx.x * 128;
    const int nc = K >> 5;

    float c[4][8][4];
    #pragma unroll
    for (int mt = 0; mt < 4; mt++)
        #pragma unroll
        for (int nt = 0; nt < 8; nt++)
            #pragma unroll
            for (int q = 0; q < 4; q++) c[mt][nt][q] = 0.0f;

    // precomputed per-lane ldmatrix offsets (relative to stage base)
    uint32_t offA[4][2], offB[2][2][2];
    {
        const int aR = lane & 15, aKb = lane >> 4;
        const int bR = (lane & 7) | ((lane >> 4) << 3);
        const int bKb = (lane >> 3) & 1;
        #pragma unroll
        for (int mt = 0; mt < 4; mt++)
            #pragma unroll
            for (int ks = 0; ks < 2; ks++)
                offA[mt][ks] = swz_addr(0, wm * 64 + mt * 16 + aR, ks * 2 + aKb);
        #pragma unroll
        for (int nh = 0; nh < 2; nh++)
            #pragma unroll
            for (int p = 0; p < 2; p++)
                #pragma unroll
                for (int ks = 0; ks < 2; ks++)
                    offB[nh][p][ks] = 8192u +
                        swz_addr(0, wn * 64 + nh * 32 + p * 16 + bR, ks * 2 + bKb);
    }

    // prologue: stages 0..2
    #pragma unroll
    for (int s = 0; s < 3; s++)
        load_stage(sb + s * STG_BYTES, Ah, Bw, bm, bn, K, s * 32, tid);

    for (int i = 0; i < nc; i++) {
        CP_WAIT(2);
        __syncthreads();
        if (i + 3 < nc)
            load_stage(sb + (uint32_t)((i + 3) & 3) * STG_BYTES, Ah, Bw,
                       bm, bn, K, (i + 3) * 32, tid);
        const uint32_t st = sb + (uint32_t)(i & 3) * STG_BYTES;
        #pragma unroll
        for (int ks = 0; ks < 2; ks++) {
            uint32_t aF[4][4];
            #pragma unroll
            for (int mt = 0; mt < 4; mt++) LDSM4(aF[mt], st + offA[mt][ks]);
            #pragma unroll
            for (int nh = 0; nh < 2; nh++) {
                uint32_t bf[2][4];
                #pragma unroll
                for (int p = 0; p < 2; p++) LDSM4(bf[p], st + offB[nh][p][ks]);
                #pragma unroll
                for (int mt = 0; mt < 4; mt++)
                    #pragma unroll
                    for (int nt = 0; nt < 4; nt++)
                        MMAF16(c[mt][nh * 4 + nt], aF[mt],
                               bf[nt >> 1][(nt & 1) * 2], bf[nt >> 1][(nt & 1) * 2 + 1]);
            }
        }
    }

    // epilogue
    #pragma unroll
    for (int mt = 0; mt < 4; mt++) {
        #pragma unroll
        for (int hh = 0; hh < 2; hh++) {
            const int m = bm + wm * 64 + mt * 16 + (lane >> 2) + hh * 8;
            const float* resRow = (RES == 1) ? (Res + (size_t)m * N)
                                : (RES == 2) ? (Res + (size_t)(m % resMod) * N)
                                : nullptr;
            #pragma unroll
            for (int nt = 0; nt < 8; nt++) {
                const int n = bn + wn * 64 + nt * 8 + (lane & 3) * 2;
                float vx = c[mt][nt][hh * 2 + 0] + bias[n + 0];
                float vy = c[mt][nt][hh * 2 + 1] + bias[n + 1];
                if (RES != 0) { vx += resRow[n + 0]; vy += resRow[n + 1]; }
                if (RELU) { vx = fmaxf(vx, 0.f); vy = fmaxf(vy, 0.f); }
                if (C) *(float2*)(C + (size_t)m * N + n) = make_float2(vx, vy);
                if (Chi)
                    *(__half2*)(Chi + (size_t)m * N + n) = __floats2half2_rn(vx, vy);
            }
        }
    }
}

// ---------------- converters ----------------
__global__ void cvt_h16(const float* __restrict__ in, __half* __restrict__ out, int n4)
{
    int i = blockIdx.x * 256 + threadIdx.x;
    if (i >= n4) return;
    float4 f = ((const float4*)in)[i];
    ((__half2*)out)[i * 2 + 0] = __floats2half2_rn(f.x, f.y);
    ((__half2*)out)[i * 2 + 1] = __floats2half2_rn(f.z, f.w);
}
__global__ void concat_bias(const float* __restrict__ bk, const float* __restrict__ bv,
                            float* __restrict__ bkv)
{
    int i = blockIdx.x * 256 + threadIdx.x;
    if (i < D_) bkv[i] = bk[i];
    else if (i < NKV_) bkv[i] = bv[i - D_];
}

// ---------------- block reductions (256 threads = 8 warps) ----------------
__device__ __forceinline__ float blockSum256(float v, float* sm) {
    #pragma unroll
    for (int o = 16; o > 0; o >>= 1) v += __shfl_xor_sync(0xffffffffu, v, o);
    const int w = threadIdx.x >> 5, lane = threadIdx.x & 31;
    if (lane == 0) sm[w] = v;
    __syncthreads();
    float r = (lane < 8) ? sm[lane] : 0.0f;
    #pragma unroll
    for (int o = 4; o > 0; o >>= 1) r += __shfl_xor_sync(0xffffffffu, r, o);
    r = __shfl_sync(0xffffffffu, r, 0);
    __syncthreads();
    return r;
}
__device__ __forceinline__ float blockMax256(float v, float* sm) {
    #pragma unroll
    for (int o = 16; o > 0; o >>= 1) v = fmaxf(v, __shfl_xor_sync(0xffffffffu, v, o));
    const int w = threadIdx.x >> 5, lane = threadIdx.x & 31;
    if (lane == 0) sm[w] = v;
    __syncthreads();
    float r = (lane < 8) ? sm[lane] : -INFINITY;
    #pragma unroll
    for (int o = 4; o > 0; o >>= 1) r = fmaxf(r, __shfl_xor_sync(0xffffffffu, r, o));
    r = __shfl_sync(0xffffffffu, r, 0);
    __syncthreads();
    return r;
}

// ---------------- row LayerNorm; optional fp16 output ----------------
__global__ void ln_rows(const float* __restrict__ X, const float* __restrict__ gg,
                        const float* __restrict__ bb, float* __restrict__ O, float alpha,
                        __half* __restrict__ Oh)
{
    __shared__ float sm[8];
    const int row = blockIdx.x;
    const float* x = X + (size_t)row * D_;
    float v[3];
    float s = 0.0f, sq = 0.0f;
    #pragma unroll
    for (int j = 0; j < 3; j++) {
        v[j] = alpha * x[threadIdx.x + j * 256];
        s += v[j]; sq += v[j] * v[j];
    }
    s  = blockSum256(s, sm);
    sq = blockSum256(sq, sm);
    const float mean = s * (1.0f / D_);
    const float var  = sq * (1.0f / D_) - mean * mean;
    const float inv  = rsqrtf(var + 1e-5f);
    float* o = O + (size_t)row * D_;
    #pragma unroll
    for (int j = 0; j < 3; j++) {
        const int i = threadIdx.x + j * 256;
        const float ov = (v[j] - mean) * inv * gg[i] + bb[i];
        o[i] = ov;
        if (Oh) Oh[(size_t)row * D_ + i] = __float2half_rn(ov);
    }
}

// ---------------- q projection (L=100 rows), folds 1/sqrt(hd) ----------------
__global__ void qproj(const float* __restrict__ t, const float* __restrict__ Wq,
                      const float* __restrict__ bq, float* __restrict__ q)
{
    const int l = blockIdx.x;
    const int e = blockIdx.y * 128 + threadIdx.x;
    __shared__ float ts[D_];
    for (int i = threadIdx.x; i < D_; i += 128) ts[i] = t[(size_t)l * D_ + i];
    __syncthreads();
    const float* w = Wq + (size_t)e * D_;
    float acc = 0.0f;
    #pragma unroll 8
    for (int d = 0; d < D_; d++) acc = fmaf(ts[d], w[d], acc);
    q[(size_t)l * D_ + e] = (acc + bq[e]) * 0.10206207261596575f;  // 1/sqrt(96)
}

// ---------------- scores: attn[b,h,l,s] = q_h[l,:] . k[b,s,h,:] (kv pitch 1536) ----
__global__ __launch_bounds__(128)
void scores_kernel(const float* __restrict__ q, const float* __restrict__ kv,
                   float* __restrict__ attn)
{
    const int bh = blockIdx.y, b = bh >> 3, h = bh & 7;
    const int s = blockIdx.x * 128 + threadIdx.x;
    __shared__ float qs[L_ * HD_];
    for (int idx = threadIdx.x; idx < L_ * HD_; idx += 128) {
        const int l = idx / HD_, e = idx - l * HD_;
        qs[idx] = q[(size_t)l * D_ + h * HD_ + e];
    }
    __syncthreads();
    const float4* kr4 = (const float4*)(kv + ((size_t)b * S_ + s) * NKV_ + h * HD_);
    float4 kreg[HD_ / 4];
    #pragma unroll
    for (int e4 = 0; e4 < HD_ / 4; e4++) kreg[e4] = kr4[e4];

    float* orow = attn + (size_t)bh * L_ * S_ + s;
    for (int l0 = 0; l0 < L_; l0 += 20) {
        float acc[20];
        #pragma unroll
        for (int i = 0; i < 20; i++) acc[i] = 0.0f;
        #pragma unroll
        for (int i = 0; i < 20; i++) {
            const float* qrow = &qs[(size_t)(l0 + i) * HD_];
            #pragma unroll
            for (int e4 = 0; e4 < HD_ / 4; e4++) {
                const float4 qq = *(const float4*)&qrow[e4 * 4];
                const float4 kk = kreg[e4];
                acc[i] = fmaf(qq.x, kk.x, acc[i]);
                acc[i] = fmaf(qq.y, kk.y, acc[i]);
                acc[i] = fmaf(qq.z, kk.z, acc[i]);
                acc[i] = fmaf(qq.w, kk.w, acc[i]);
            }
        }
        #pragma unroll
        for (int i = 0; i < 20; i++) orow[(size_t)(l0 + i) * S_] = acc[i];
    }
}

// ---------------- softmax in place + head-mean a_score ----------------
__global__ void softmax_mean(float* __restrict__ attn, float* __restrict__ ascore)
{
    __shared__ float sm[8];
    const int l = blockIdx.x, b = blockIdx.y;
    const int tid = threadIdx.x;
    float am[4] = {0.f, 0.f, 0.f, 0.f};
    for (int h = 0; h < H_; h++) {
        float* row = attn + (((size_t)(b * H_ + h)) * L_ + l) * S_;
        float v[4];
        float mx = -INFINITY;
        #pragma unroll
        for (int j = 0; j < 4; j++) { v[j] = row[tid + j * 256]; mx = fmaxf(mx, v[j]); }
        mx = blockMax256(mx, sm);
        float ssum = 0.0f;
        #pragma unroll
        for (int j = 0; j < 4; j++) { v[j] = expf(v[j] - mx); ssum += v[j]; }
        ssum = blockSum256(ssum, sm);
        const float inv = 1.0f / ssum;
        #pragma unroll
        for (int j = 0; j < 4; j++) {
            const float p = v[j] * inv;
            row[tid + j * 256] = p;
            am[j] += p * (1.0f / H_);
        }
    }
    float* ao = ascore + ((size_t)b * L_ + l) * S_;
    #pragma unroll
    for (int j = 0; j < 4; j++) ao[tid + j * 256] = am[j];
}

// ---------------- ao[b,l,h,:] = attn[b,h,l,:] @ v[b,:,h,:]; fp16 output ----------------
#define AV_ST 32
__global__ __launch_bounds__(256)
void attn_v(const float* __restrict__ attn, const float* __restrict__ kv,
            __half* __restrict__ aoh)
{
    const int bh = blockIdx.x, b = bh >> 3, h = bh & 7;
    const float* A = attn + (size_t)bh * L_ * S_;
    const float* V = kv + (size_t)b * S_ * NKV_ + D_ + h * HD_;
    __shared__ float As[AV_ST][113];
    __shared__ float Vs[AV_ST][HD_];
    const int tid = threadIdx.x;
    const int tx = tid & 15, ty = tid >> 4;
    float acc[7][6];
    #pragma unroll
    for (int i = 0; i < 7; i++)
        #pragma unroll
        for (int j = 0; j < 6; j++) acc[i][j] = 0.0f;

    for (int idx = tid; idx < AV_ST * 13; idx += 256)
        As[idx / 13][100 + idx % 13] = 0.0f;

    for (int s0 = 0; s0 < S_; s0 += AV_ST) {
        for (int idx = tid; idx < L_ * AV_ST; idx += 256) {
            const int m = idx / AV_ST, ss = idx - m * AV_ST;
            As[ss][m] = A[(size_t)m * S_ + s0 + ss];
        }
        for (int idx = tid; idx < AV_ST * HD_; idx += 256) {
            const int r = idx / HD_, cc = idx - r * HD_;
            Vs[r][cc] = V[(size_t)(s0 + r) * NKV_ + cc];
        }
        __syncthreads();
        #pragma unroll 4
        for (int ss = 0; ss < AV_ST; ss++) {
            float ra[7], rb[6];
            #pragma unroll
            for (int i = 0; i < 7; i++) ra[i] = As[ss][ty + 16 * i];
            #pragma unroll
            for (int j = 0; j < 6; j++) rb[j] = Vs[ss][tx + 16 * j];
            #pragma unroll
            for (int i = 0; i < 7; i++)
                #pragma unroll
                for (int j = 0; j < 6; j++)
                    acc[i][j] = fmaf(ra[i], rb[j], acc[i][j]);
        }
        __syncthreads();
    }
    #pragma unroll
    for (int i = 0; i < 7; i++) {
        const int m = ty + 16 * i;
        if (m < L_) {
            const size_t base = ((size_t)b * L_ + m) * D_ + h * HD_;
            #pragma unroll
            for (int j = 0; j < 6; j++)
                aoh[base + tx + 16 * j] = __float2half_rn(acc[i][j]);
        }
    }
}

// ---------------- GroupFC batch-independent term + bias ----------------
__global__ void yterm_kernel(const float* __restrict__ y, const float* __restrict__ dp,
                             const float* __restrict__ dbias, float* __restrict__ yt)
{
    const int l = blockIdx.x;
    const int w = threadIdx.x >> 5, lane = threadIdx.x & 31;
    const float* dpl = dp + (size_t)l * (2 * D_) * DF_ + (size_t)D_ * DF_ + w;
    const float* yr = y + (size_t)l * D_;
    float acc = 0.0f;
    for (int d = lane; d < D_; d += 32) acc = fmaf(yr[d], dpl[(size_t)d * DF_], acc);
    #pragma unroll
    for (int o = 16; o > 0; o >>= 1) acc += __shfl_xor_sync(0xffffffffu, acc, o);
    if (lane == 0) yt[l * DF_ + w] = acc + dbias[l * DF_ + w];
}

// ---------------- logits ----------------
__global__ void logits_kernel(const float* __restrict__ hh, const float* __restrict__ dp,
                              const float* __restrict__ yt, float* __restrict__ out)
{
    const int l = blockIdx.x, b = blockIdx.y;
    const int w = threadIdx.x >> 5, lane = threadIdx.x & 31;
    __shared__ float hs[D_];
    for (int i = threadIdx.x; i < D_; i += 320) hs[i] = hh[((size_t)b * L_ + l) * D_ + i];
    __syncthreads();
    const float* dpl = dp + (size_t)l * (2 * D_) * DF_ + w;
    float acc = 0.0f;
    for (int d = lane; d < D_; d += 32) acc = fmaf(hs[d], dpl[(size_t)d * DF_], acc);
    #pragma unroll
    for (int o = 16; o > 0; o >>= 1) acc += __shfl_xor_sync(0xffffffffu, acc, o);
    if (lane == 0) out[(size_t)b * C_ + l * DF_ + w] = acc + yt[l * DF_ + w];
}

// ---------------- host launch ----------------
extern "C" void kernel_launch(void* const* d_in, const int* in_sizes, int n_in,
                              void* d_out, int out_size)
{
    const float* x       = (const float*)d_in[0];
    const float* y       = (const float*)d_in[1];
    const float* embed_W = (const float*)d_in[2];
    const float* embed_b = (const float*)d_in[3];
    const float* Wq      = (const float*)d_in[4];
    const float* Wk      = (const float*)d_in[5];
    const float* Wv      = (const float*)d_in[6];
    const float* bq      = (const float*)d_in[7];
    const float* bk      = (const float*)d_in[8];
    const float* bv      = (const float*)d_in[9];
    const float* Wo      = (const float*)d_in[10];
    const float* bo      = (const float*)d_in[11];
    const float* ln1_g   = (const float*)d_in[12];
    const float* ln1_b   = (const float*)d_in[13];
    const float* ln2_g   = (const float*)d_in[14];
    const float* ln2_b   = (const float*)d_in[15];
    const float* ln3_g   = (const float*)d_in[16];
    const float* ln3_b   = (const float*)d_in[17];
    const float* W1      = (const float*)d_in[18];
    const float* b1      = (const float*)d_in[19];
    const float* W2      = (const float*)d_in[20];
    const float* b2      = (const float*)d_in[21];
    const float* dp      = (const float*)d_in[22];
    const float* dbias   = (const float*)d_in[23];
    float* out = (float*)d_out;

    float *pt, *pq, *pattn, *pkv, *px2, *pt2, *px3, *ph, *pyt, *pbkv, *pdump;
    __half *pxh, *pmemh, *paoh, *pt2h, *pf1h, *pwemb, *pwkv, *pwo, *pw1, *pw2;
    cudaGetSymbolAddress((void**)&pt,    g_t);
    cudaGetSymbolAddress((void**)&pq,    g_q);
    cudaGetSymbolAddress((void**)&pattn, g_attn);
    cudaGetSymbolAddress((void**)&pkv,   g_kv);
    cudaGetSymbolAddress((void**)&px2,   g_x2);
    cudaGetSymbolAddress((void**)&pt2,   g_t2);
    cudaGetSymbolAddress((void**)&px3,   g_x3);
    cudaGetSymbolAddress((void**)&ph,    g_h);
    cudaGetSymbolAddress((void**)&pyt,   g_yt);
    cudaGetSymbolAddress((void**)&pbkv,  g_bkv);
    cudaGetSymbolAddress((void**)&pdump, g_ascdump);
    cudaGetSymbolAddress((void**)&pxh,   g_xh);
    cudaGetSymbolAddress((void**)&pmemh, g_memh);
    cudaGetSymbolAddress((void**)&paoh,  g_aoh);
    cudaGetSymbolAddress((void**)&pt2h,  g_t2h);
    cudaGetSymbolAddress((void**)&pf1h,  g_f1h);
    cudaGetSymbolAddress((void**)&pwemb, g_wemb);
    cudaGetSymbolAddress((void**)&pwkv,  g_wkv);
    cudaGetSymbolAddress((void**)&pwo,   g_wo);
    cudaGetSymbolAddress((void**)&pw1,   g_w1);
    cudaGetSymbolAddress((void**)&pw2,   g_w2);

    cudaFuncSetAttribute(gemm16<true, 0>,  cudaFuncAttributeMaxDynamicSharedMemorySize, GM_SMEM);
    cudaFuncSetAttribute(gemm16<false, 0>, cudaFuncAttributeMaxDynamicSharedMemorySize, GM_SMEM);
    cudaFuncSetAttribute(gemm16<false, 1>, cudaFuncAttributeMaxDynamicSharedMemorySize, GM_SMEM);
    cudaFuncSetAttribute(gemm16<false, 2>, cudaFuncAttributeMaxDynamicSharedMemorySize, GM_SMEM);

    float* asc = (out_size >= B_ * C_ + B_ * L_ * S_) ? (out + B_ * C_) : pdump;

    // ---- operand conversion (all single-plane fp16) ----
    cvt_h16<<<(BS_ * F0_ / 4 + 255) / 256, 256>>>(x, pxh, BS_ * F0_ / 4);
    cvt_h16<<<(D_ * F0_ / 4 + 255) / 256, 256>>>(embed_W, pwemb, D_ * F0_ / 4);
    cvt_h16<<<(D_ * D_ / 4 + 255) / 256, 256>>>(Wk, pwkv, D_ * D_ / 4);
    cvt_h16<<<(D_ * D_ / 4 + 255) / 256, 256>>>(Wv, pwkv + (size_t)D_ * D_, D_ * D_ / 4);
    cvt_h16<<<(D_ * D_ / 4 + 255) / 256, 256>>>(Wo, pwo, D_ * D_ / 4);
    cvt_h16<<<(D_ * D_ / 4 + 255) / 256, 256>>>(W1, pw1, D_ * D_ / 4);
    cvt_h16<<<(D_ * D_ / 4 + 255) / 256, 256>>>(W2, pw2, D_ * D_ / 4);
    concat_bias<<<(NKV_ + 255) / 256, 256>>>(bk, bv, pbkv);

    // ---- batch-independent preamble ----
    ln_rows<<<L_, 256>>>(y, ln1_g, ln1_b, pt, 2.0f, nullptr);              // t = LN(2y)
    qproj<<<dim3(L_, D_ / 128), 128>>>(pt, Wq, bq, pq);
    yterm_kernel<<<L_, 320>>>(y, dp, dbias, pyt);

    // ---- mem = relu(x @ We^T + eb) -> fp16 ----
    gemm16<true, 0><<<dim3(D_ / 128, BS_ / 128), 128, GM_SMEM>>>(
        pxh, pwemb, embed_b, nullptr, nullptr, pmemh, BS_, D_, F0_, 0);

    // ---- fused K|V GEMM -> fp32 kv (pitch 1536) ----
    gemm16<false, 0><<<dim3(NKV_ / 128, BS_ / 128), 128, GM_SMEM>>>(
        pmemh, pwkv, pbkv, nullptr, pkv, nullptr, BS_, NKV_, D_, 0);

    // ---- attention ----
    scores_kernel<<<dim3(S_ / 128, B_ * H_), 128>>>(pq, pkv, pattn);
    softmax_mean<<<dim3(L_, B_), 256>>>(pattn, asc);
    attn_v<<<B_ * H_, 256>>>(pattn, pkv, paoh);

    // ---- out-proj + residual t[l], LN2 (fp32 + fp16) ----
    gemm16<false, 2><<<dim3(D_ / 128, BL_ / 128), 128, GM_SMEM>>>(
        paoh, pwo, bo, pt, px2, nullptr, BL_, D_, D_, L_);
    ln_rows<<<BL_, 256>>>(px2, ln2_g, ln2_b, pt2, 1.0f, pt2h);

    // ---- FFN ----
    gemm16<true, 0><<<dim3(D_ / 128, BL_ / 128), 128, GM_SMEM>>>(
        pt2h, pw1, b1, nullptr, nullptr, pf1h, BL_, D_, D_, 0);
    gemm16<false, 1><<<dim3(D_ / 128, BL_ / 128), 128, GM_SMEM>>>(
        pf1h, pw2, b2, pt2, px3, nullptr, BL_, D_, D_, 0);
    ln_rows<<<BL_, 256>>>(px3, ln3_g, ln3_b, ph, 1.0f, nullptr);

    // ---- GroupFC logits ----
    logits_kernel<<<dim3(L_, B_), 320>>>(ph, dp, pyt, out);
}

// round 10
// speedup vs baseline: 4.3568x; 1.2841x over previous
#include <cuda_runtime.h>
#include <cuda_fp16.h>
#include <math.h>
#include <stdint.h>

#define B_  32
#define S_  1024
#define F0_ 2048
#define D_  768
#define L_  100
#define H_  8
#define HD_ 96
#define DF_ 10
#define C_  1000
#define BL_ (B_*L_)   // 3200
#define BS_ (B_*S_)   // 32768
#define NKV_ 1536
#define LP_ 128       // L padded to 128

// ---------------- scratch (static __device__, zero-initialized) ----------------
static __device__ __align__(128) float g_t  [L_*D_];
static __device__ __align__(128) float g_x2 [(size_t)BL_*D_];
static __device__ __align__(128) float g_t2 [(size_t)BL_*D_];
static __device__ __align__(128) float g_x3 [(size_t)BL_*D_];
static __device__ __align__(128) float g_h  [(size_t)BL_*D_];
static __device__ __align__(128) float g_yt [C_];
static __device__ __align__(128) float g_bkv[NKV_];
static __device__ __align__(128) float g_ascdump[(size_t)B_*L_*S_];

// fp16 planes
static __device__ __align__(128) __half g_q16 [H_*LP_*HD_];            // padded q, scale folded
static __device__ __align__(128) __half g_s16 [(size_t)B_*H_*LP_*S_]; // scores -> probs (in place)
static __device__ __align__(128) __half g_kv16[(size_t)BS_*NKV_];     // k | v fp16, pitch 1536
static __device__ __align__(128) __half g_xh  [(size_t)BS_*F0_];
static __device__ __align__(128) __half g_memh[(size_t)BS_*D_];
static __device__ __align__(128) __half g_aoh [(size_t)BL_*D_];
static __device__ __align__(128) __half g_t2h [(size_t)BL_*D_];
static __device__ __align__(128) __half g_f1h [(size_t)BL_*D_];
static __device__ __align__(128) __half g_wemb[(size_t)D_*F0_];
static __device__ __align__(128) __half g_wkv [(size_t)NKV_*D_];
static __device__ __align__(128) __half g_wo  [(size_t)D_*D_];
static __device__ __align__(128) __half g_w1  [(size_t)D_*D_];
static __device__ __align__(128) __half g_w2  [(size_t)D_*D_];

// ============================================================================
// PTX helpers (sm_80-era baseline; safe on non-'a' compute_103 PTX target)
// ============================================================================
__device__ __forceinline__ uint32_t smem_u32(const void* p) {
    uint32_t a;
    asm("{ .reg .u64 t; cvta.to.shared.u64 t, %1; cvt.u32.u64 %0, t; }" : "=r"(a) : "l"(p));
    return a;
}
#define LDSM4(r, addr)                                                            \
    asm volatile("ldmatrix.sync.aligned.m8n8.x4.shared.b16 {%0,%1,%2,%3}, [%4];"  \
        : "=r"((r)[0]), "=r"((r)[1]), "=r"((r)[2]), "=r"((r)[3]) : "r"(addr))
#define MMAF16(c, a, b0, b1)                                                      \
    asm volatile("mma.sync.aligned.m16n8k16.row.col.f32.f16.f16.f32 "             \
        "{%0,%1,%2,%3}, {%4,%5,%6,%7}, {%8,%9}, {%0,%1,%2,%3};"                   \
        : "+f"((c)[0]), "+f"((c)[1]), "+f"((c)[2]), "+f"((c)[3])                  \
        : "r"((a)[0]), "r"((a)[1]), "r"((a)[2]), "r"((a)[3]), "r"(b0), "r"(b1))
#define CP16(dst, src)                                                            \
    asm volatile("cp.async.cg.shared.global [%0], [%1], 16;" :: "r"(dst), "l"(src))
#define CP_COMMIT() asm volatile("cp.async.commit_group;" ::: "memory")
#define CP_WAIT(n)  asm volatile("cp.async.wait_group %0;" :: "n"(n) : "memory")

// swizzle for 64B logical rows packed 2-per-128B line (conflict-free ldmatrix)
__device__ __forceinline__ uint32_t swz_addr(uint32_t base, int r, int kb) {
    uint32_t line = (uint32_t)r >> 1;
    uint32_t slot = ((((uint32_t)r & 1u) << 2) | (uint32_t)kb) ^ (line & 7u);
    return base + line * 128u + slot * 16u;
}

// fast exp on FMA pipe: exp(x) = 2^(x*log2e), deg-5 Taylor for 2^f, |f|<=0.5
__device__ __forceinline__ float fexp(float x) {
    float p = x * 1.4426950408889634f;
    p = fmaxf(p, -120.0f);
    float nf = rintf(p);
    float f = p - nf;
    float r = 0.0013333558146428443f;
    r = fmaf(r, f, 0.009618129107628477f);
    r = fmaf(r, f, 0.05550410866482158f);
    r = fmaf(r, f, 0.2402265069591007f);
    r = fmaf(r, f, 0.6931471805599453f);
    r = fmaf(r, f, 1.0f);
    return r * __int_as_float(((int)nf + 127) << 23);
}

// ============================================================================
// Generalized 1-pass fp16 HMMA GEMM: C = act(A * B^T + bias [+ res])
// Strided A/B/C; per-blockIdx.z offsets: h=z&7, b=z>>3:
//   A += h*oAh;  B += b*oBb + h*oBh;  C/Chi += z*oC.
// ============================================================================
#define NSTG 4
#define STG_BYTES 16384u
#define GM_SMEM (NSTG * STG_BYTES)   // 65536

__device__ __forceinline__ void load_stage(uint32_t sbase,
    const __half* __restrict__ Ah, const __half* __restrict__ Bw,
    int bm, int bn, int lda, int ldb, int k0, int row)
{
    const __half* pa = Ah + (size_t)(bm + row) * lda + k0;
    const __half* pb = Bw + (size_t)(bn + row) * ldb + k0;
    #pragma unroll
    for (int kb = 0; kb < 4; kb++) {
        CP16(swz_addr(sbase, row, kb),          pa + kb * 8);
        CP16(swz_addr(sbase + 8192u, row, kb),  pb + kb * 8);
    }
    CP_COMMIT();
}

template<bool RELU, int RES, bool BIAS>
__global__ void __launch_bounds__(128, 2)
gemm16(const __half* __restrict__ Ah, const __half* __restrict__ Bw,
       const float* __restrict__ bias, const float* __restrict__ Res,
       float* __restrict__ C, __half* __restrict__ Chi,
       int K, int lda, int ldb, int ldc, int resMod,
       size_t oAh, size_t oBb, size_t oBh, size_t oC)
{
    extern __shared__ char smem[];
    const uint32_t sb = smem_u32(smem);
    const int tid = threadIdx.x, lane = tid & 31, wid = tid >> 5;
    const int wm = wid & 1, wn = wid >> 1;
    const int bm = blockIdx.y * 128, bn = blockIdx.x * 128;
    const int z = blockIdx.z, hz = z & 7, bz = z >> 3;
    Ah += (size_t)hz * oAh;
    Bw += (size_t)bz * oBb + (size_t)hz * oBh;
    const size_t coff = (size_t)z * oC;
    const int nc = K >> 5;

    float c[4][8][4];
    #pragma unroll
    for (int mt = 0; mt < 4; mt++)
        #pragma unroll
        for (int nt = 0; nt < 8; nt++)
            #pragma unroll
            for (int q = 0; q < 4; q++) c[mt][nt][q] = 0.0f;

    uint32_t offA[4][2], offB[2][2][2];
    {
        const int aR = lane & 15, aKb = lane >> 4;
        const int bR = (lane & 7) | ((lane >> 4) << 3);
        const int bKb = (lane >> 3) & 1;
        #pragma unroll
        for (int mt = 0; mt < 4; mt++)
            #pragma unroll
            for (int ks = 0; ks < 2; ks++)
                offA[mt][ks] = swz_addr(0, wm * 64 + mt * 16 + aR, ks * 2 + aKb);
        #pragma unroll
        for (int nh = 0; nh < 2; nh++)
            #pragma unroll
            for (int p = 0; p < 2; p++)
                #pragma unroll
                for (int ks = 0; ks < 2; ks++)
                    offB[nh][p][ks] = 8192u +
                        swz_addr(0, wn * 64 + nh * 32 + p * 16 + bR, ks * 2 + bKb);
    }

    #pragma unroll
    for (int s = 0; s < 3; s++)
        load_stage(sb + s * STG_BYTES, Ah, Bw, bm, bn, lda, ldb, s * 32, tid);

    for (int i = 0; i < nc; i++) {
        CP_WAIT(2);
        __syncthreads();
        if (i + 3 < nc)
            load_stage(sb + (uint32_t)((i + 3) & 3) * STG_BYTES, Ah, Bw,
                       bm, bn, lda, ldb, (i + 3) * 32, tid);
        else
            CP_COMMIT();     // keep group count exact (no tail race)
        const uint32_t st = sb + (uint32_t)(i & 3) * STG_BYTES;
        #pragma unroll
        for (int ks = 0; ks < 2; ks++) {
            uint32_t aF[4][4];
            #pragma unroll
            for (int mt = 0; mt < 4; mt++) LDSM4(aF[mt], st + offA[mt][ks]);
            #pragma unroll
            for (int nh = 0; nh < 2; nh++) {
                uint32_t bf[2][4];
                #pragma unroll
                for (int p = 0; p < 2; p++) LDSM4(bf[p], st + offB[nh][p][ks]);
                #pragma unroll
                for (int mt = 0; mt < 4; mt++)
                    #pragma unroll
                    for (int nt = 0; nt < 4; nt++)
                        MMAF16(c[mt][nh * 4 + nt], aF[mt],
                               bf[nt >> 1][(nt & 1) * 2], bf[nt >> 1][(nt & 1) * 2 + 1]);
            }
        }
    }

    #pragma unroll
    for (int mt = 0; mt < 4; mt++) {
        #pragma unroll
        for (int hh = 0; hh < 2; hh++) {
            const int m = bm + wm * 64 + mt * 16 + (lane >> 2) + hh * 8;
            const float* resRow = (RES == 1) ? (Res + (size_t)m * ldc)
                                : (RES == 2) ? (Res + (size_t)(m % resMod) * ldc)
                                : nullptr;
            #pragma unroll
            for (int nt = 0; nt < 8; nt++) {
                const int n = bn + wn * 64 + nt * 8 + (lane & 3) * 2;
                float vx = c[mt][nt][hh * 2 + 0];
                float vy = c[mt][nt][hh * 2 + 1];
                if (BIAS) { vx += bias[n]; vy += bias[n + 1]; }
                if (RES != 0) { vx += resRow[n]; vy += resRow[n + 1]; }
                if (RELU) { vx = fmaxf(vx, 0.f); vy = fmaxf(vy, 0.f); }
                if (C) *(float2*)(C + coff + (size_t)m * ldc + n) = make_float2(vx, vy);
                if (Chi)
                    *(__half2*)(Chi + coff + (size_t)m * ldc + n) = __floats2half2_rn(vx, vy);
            }
        }
    }
}

// ============================================================================
// attn_v: ao[b,l,h*96+:] = probs[bh,l,:] @ V[b,:,h*96+:]  via HMMA
// Per-(b,h) GEMM M=128(pad) x N=96 x K=1024; V transposed into smem [hd][s].
// ============================================================================
#define AVS_A 8192u
#define AVS_V 6144u
#define AV_SMEM (4u*AVS_A + 2u*AVS_V)   // 45056

__global__ void __launch_bounds__(128, 2)
attn_v_mma(const __half* __restrict__ probs, const __half* __restrict__ kv16,
           __half* __restrict__ aoh)
{
    extern __shared__ char smem[];
    const uint32_t sb = smem_u32(smem);
    const int tid = threadIdx.x, lane = tid & 31, wid = tid >> 5;
    const int wm = wid & 1, wn = wid >> 1;
    const int bh = blockIdx.x, b = bh >> 3, h = bh & 7;
    const __half* A = probs + (size_t)bh * LP_ * S_;
    const __half* V = kv16 + (size_t)b * S_ * NKV_ + D_ + h * HD_;

    float c[4][6][4];
    #pragma unroll
    for (int mt = 0; mt < 4; mt++)
        #pragma unroll
        for (int nt = 0; nt < 6; nt++)
            #pragma unroll
            for (int q = 0; q < 4; q++) c[mt][nt][q] = 0.0f;

    uint32_t offA[4][2], offB[3][2];
    {
        const int aR = lane & 15, aKb = lane >> 4;
        #pragma unroll
        for (int mt = 0; mt < 4; mt++)
            #pragma unroll
            for (int ks = 0; ks < 2; ks++)
                offA[mt][ks] = swz_addr(0, wm * 64 + mt * 16 + aR, ks * 2 + aKb);
        const int bR = (lane & 7) | ((lane >> 4) << 3);
        const int bKb = (lane >> 3) & 1;
        #pragma unroll
        for (int nb = 0; nb < 3; nb++)
            #pragma unroll
            for (int ks = 0; ks < 2; ks++)
                offB[nb][ks] = swz_addr(0, wn * 48 + nb * 16 + bR, ks * 2 + bKb);
    }

    // per-thread V quad coordinates: 6 quads of (2 s-rows x 2 hd-cols)
    int qs[6], qh[6];
    #pragma unroll
    for (int q = 0; q < 6; q++) {
        const int idx = tid + q * 128;            // 0..767
        qs[q] = (idx / 48) * 2;                   // s_local 0..30 even
        qh[q] = (idx % 48) * 2;                   // hd 0..94 even
    }

    uint32_t vlo[6], vhi[6];
    const int nChunks = S_ / 32;                  // 32

    // prologue
    #pragma unroll
    for (int s = 0; s < 3; s++) {
        const __half* pa = A + (size_t)tid * S_ + s * 32;
        const uint32_t dst = sb + (uint32_t)s * AVS_A;
        #pragma unroll
        for (int kb = 0; kb < 4; kb++) CP16(swz_addr(dst, tid, kb), pa + kb * 8);
        CP_COMMIT();
    }
    {   // V chunk 0
        #pragma unroll
        for (int q = 0; q < 6; q++) {
            const __half* p = V + (size_t)qs[q] * NKV_ + qh[q];
            const uint32_t v0 = *(const uint32_t*)p;
            const uint32_t v1 = *(const uint32_t*)(p + NKV_);
            vlo[q] = __byte_perm(v0, v1, 0x5410);
            vhi[q] = __byte_perm(v0, v1, 0x7632);
        }
        char* vbuf = smem + 4 * AVS_A;
        #pragma unroll
        for (int q = 0; q < 6; q++) {
            const uint32_t o0 = swz_addr(0, qh[q],     qs[q] >> 3) + ((qs[q] * 2) & 15);
            const uint32_t o1 = swz_addr(0, qh[q] + 1, qs[q] >> 3) + ((qs[q] * 2) & 15);
            *(uint32_t*)(vbuf + o0) = vlo[q];
            *(uint32_t*)(vbuf + o1) = vhi[q];
        }
    }
    CP_WAIT(2);
    __syncthreads();

    for (int i = 0; i < nChunks; i++) {
        // 1. prefetch V regs for chunk i+1
        if (i + 1 < nChunks) {
            const int k0 = (i + 1) * 32;
            #pragma unroll
            for (int q = 0; q < 6; q++) {
                const __half* p = V + (size_t)(k0 + qs[q]) * NKV_ + qh[q];
                const uint32_t v0 = *(const uint32_t*)p;
                const uint32_t v1 = *(const uint32_t*)(p + NKV_);
                vlo[q] = __byte_perm(v0, v1, 0x5410);
                vhi[q] = __byte_perm(v0, v1, 0x7632);
            }
        }
        // 2. MMA chunk i
        const uint32_t stA = sb + (uint32_t)(i & 3) * AVS_A;
        const uint32_t stV = sb + 4u * AVS_A + (uint32_t)(i & 1) * AVS_V;
        #pragma unroll
        for (int ks = 0; ks < 2; ks++) {
            uint32_t aF[4][4], bf[3][4];
            #pragma unroll
            for (int mt = 0; mt < 4; mt++) LDSM4(aF[mt], stA + offA[mt][ks]);
            #pragma unroll
            for (int nb = 0; nb < 3; nb++) LDSM4(bf[nb], stV + offB[nb][ks]);
            #pragma unroll
            for (int mt = 0; mt < 4; mt++)
                #pragma unroll
                for (int nt = 0; nt < 6; nt++)
                    MMAF16(c[mt][nt], aF[mt],
                           bf[nt >> 1][(nt & 1) * 2], bf[nt >> 1][(nt & 1) * 2 + 1]);
        }
        // 3. next A chunk (or empty commit to keep count exact)
        if (i + 3 < nChunks) {
            const __half* pa = A + (size_t)tid * S_ + (i + 3) * 32;
            const uint32_t dst = sb + (uint32_t)((i + 3) & 3) * AVS_A;
            #pragma unroll
            for (int kb = 0; kb < 4; kb++) CP16(swz_addr(dst, tid, kb), pa + kb * 8);
        }
        CP_COMMIT();
        // 4. STS V chunk i+1 into the other buffer
        if (i + 1 < nChunks) {
            char* vbuf = smem + 4 * AVS_A + ((i + 1) & 1) * AVS_V;
            #pragma unroll
            for (int q = 0; q < 6; q++) {
                const uint32_t o0 = swz_addr(0, qh[q],     qs[q] >> 3) + ((qs[q] * 2) & 15);
                const uint32_t o1 = swz_addr(0, qh[q] + 1, qs[q] >> 3) + ((qs[q] * 2) & 15);
                *(uint32_t*)(vbuf + o0) = vlo[q];
                *(uint32_t*)(vbuf + o1) = vhi[q];
            }
        }
        // 5. advance pipeline
        if (i + 1 < nChunks) {
            CP_WAIT(2);
            __syncthreads();
        }
    }

    // epilogue: masked rows m<100
    #pragma unroll
    for (int mt = 0; mt < 4; mt++) {
        #pragma unroll
        for (int hh = 0; hh < 2; hh++) {
            const int m = wm * 64 + mt * 16 + (lane >> 2) + hh * 8;
            if (m < L_) {
                __half* orow = aoh + ((size_t)b * L_ + m) * D_ + h * HD_;
                #pragma unroll
                for (int nt = 0; nt < 6; nt++) {
                    const int n = wn * 48 + nt * 8 + (lane & 3) * 2;
                    *(__half2*)(orow + n) =
                        __floats2half2_rn(c[mt][nt][hh * 2], c[mt][nt][hh * 2 + 1]);
                }
            }
        }
    }
}

// ---------------- converters ----------------
__global__ void cvt_h16(const float* __restrict__ in, __half* __restrict__ out, int n4)
{
    int i = blockIdx.x * 256 + threadIdx.x;
    if (i >= n4) return;
    float4 f = ((const float4*)in)[i];
    ((__half2*)out)[i * 2 + 0] = __floats2half2_rn(f.x, f.y);
    ((__half2*)out)[i * 2 + 1] = __floats2half2_rn(f.z, f.w);
}
__global__ void concat_bias(const float* __restrict__ bk, const float* __restrict__ bv,
                            float* __restrict__ bkv)
{
    int i = blockIdx.x * 256 + threadIdx.x;
    if (i < D_) bkv[i] = bk[i];
    else if (i < NKV_) bkv[i] = bv[i - D_];
}

// ---------------- block reduction ----------------
__device__ __forceinline__ float blockSum256(float v, float* sm) {
    #pragma unroll
    for (int o = 16; o > 0; o >>= 1) v += __shfl_xor_sync(0xffffffffu, v, o);
    const int w = threadIdx.x >> 5, lane = threadIdx.x & 31;
    if (lane == 0) sm[w] = v;
    __syncthreads();
    float r = (lane < 8) ? sm[lane] : 0.0f;
    #pragma unroll
    for (int o = 4; o > 0; o >>= 1) r += __shfl_xor_sync(0xffffffffu, r, o);
    r = __shfl_sync(0xffffffffu, r, 0);
    __syncthreads();
    return r;
}

// ---------------- row LayerNorm; optional fp16 output ----------------
__global__ void ln_rows(const float* __restrict__ X, const float* __restrict__ gg,
                        const float* __restrict__ bb, float* __restrict__ O, float alpha,
                        __half* __restrict__ Oh)
{
    __shared__ float sm[8];
    const int row = blockIdx.x;
    const float* x = X + (size_t)row * D_;
    float v[3];
    float s = 0.0f, sq = 0.0f;
    #pragma unroll
    for (int j = 0; j < 3; j++) {
        v[j] = alpha * x[threadIdx.x + j * 256];
        s += v[j]; sq += v[j] * v[j];
    }
    s  = blockSum256(s, sm);
    sq = blockSum256(sq, sm);
    const float mean = s * (1.0f / D_);
    const float var  = sq * (1.0f / D_) - mean * mean;
    const float inv  = rsqrtf(var + 1e-5f);
    float* o = O + (size_t)row * D_;
    #pragma unroll
    for (int j = 0; j < 3; j++) {
        const int i = threadIdx.x + j * 256;
        const float ov = (v[j] - mean) * inv * gg[i] + bb[i];
        o[i] = ov;
        if (Oh) Oh[(size_t)row * D_ + i] = __float2half_rn(ov);
    }
}

// ---------------- q projection -> fp16 padded [H][128][96], scale folded ----------------
__global__ void qproj(const float* __restrict__ t, const float* __restrict__ Wq,
                      const float* __restrict__ bq, __half* __restrict__ q16)
{
    const int l = blockIdx.x;
    const int e = blockIdx.y * 128 + threadIdx.x;
    __shared__ float ts[D_];
    for (int i = threadIdx.x; i < D_; i += 128) ts[i] = t[(size_t)l * D_ + i];
    __syncthreads();
    const float* w = Wq + (size_t)e * D_;
    float acc = 0.0f;
    #pragma unroll 8
    for (int d = 0; d < D_; d++) acc = fmaf(ts[d], w[d], acc);
    const float val = (acc + bq[e]) * 0.10206207261596575f;   // 1/sqrt(96)
    const int hh = e / HD_, eh = e - hh * HD_;
    q16[(size_t)hh * LP_ * HD_ + (size_t)l * HD_ + eh] = __float2half_rn(val);
    // pad rows (l=100..127) stay zero from static init
}

// ---------------- softmax in place (fp16 scores->probs) + head-mean a_score ----
__global__ void softmax_mean(__half* __restrict__ s16, float* __restrict__ ascore)
{
    __shared__ float sm[8];
    const int l = blockIdx.x, b = blockIdx.y;
    const int tid = threadIdx.x;
    float am[4] = {0.f, 0.f, 0.f, 0.f};
    for (int h = 0; h < H_; h++) {
        __half* row = s16 + ((size_t)(b * H_ + h) * LP_ + l) * S_;
        float v[4];
        #pragma unroll
        for (int j = 0; j < 4; j++) v[j] = __half2float(row[tid + j * 256]);
        // scores are O(1): exp without max-subtraction is numerically safe
        float ssum = 0.0f;
        #pragma unroll
        for (int j = 0; j < 4; j++) { v[j] = fexp(v[j]); ssum += v[j]; }
        ssum = blockSum256(ssum, sm);
        const float inv = 1.0f / ssum;
        #pragma unroll
        for (int j = 0; j < 4; j++) {
            const float p = v[j] * inv;
            row[tid + j * 256] = __float2half_rn(p);
            am[j] += p * (1.0f / H_);
        }
    }
    float* ao = ascore + ((size_t)b * L_ + l) * S_;
    #pragma unroll
    for (int j = 0; j < 4; j++) ao[tid + j * 256] = am[j];
}

// ---------------- GroupFC batch-independent term + bias ----------------
__global__ void yterm_kernel(const float* __restrict__ y, const float* __restrict__ dp,
                             const float* __restrict__ dbias, float* __restrict__ yt)
{
    const int l = blockIdx.x;
    const int w = threadIdx.x >> 5, lane = threadIdx.x & 31;
    const float* dpl = dp + (size_t)l * (2 * D_) * DF_ + (size_t)D_ * DF_ + w;
    const float* yr = y + (size_t)l * D_;
    float acc = 0.0f;
    for (int d = lane; d < D_; d += 32) acc = fmaf(yr[d], dpl[(size_t)d * DF_], acc);
    #pragma unroll
    for (int o = 16; o > 0; o >>= 1) acc += __shfl_xor_sync(0xffffffffu, acc, o);
    if (lane == 0) yt[l * DF_ + w] = acc + dbias[l * DF_ + w];
}

// ---------------- logits ----------------
__global__ void logits_kernel(const float* __restrict__ hh, const float* __restrict__ dp,
                              const float* __restrict__ yt, float* __restrict__ out)
{
    const int l = blockIdx.x, b = blockIdx.y;
    const int w = threadIdx.x >> 5, lane = threadIdx.x & 31;
    __shared__ float hs[D_];
    for (int i = threadIdx.x; i < D_; i += 320) hs[i] = hh[((size_t)b * L_ + l) * D_ + i];
    __syncthreads();
    const float* dpl = dp + (size_t)l * (2 * D_) * DF_ + w;
    float acc = 0.0f;
    for (int d = lane; d < D_; d += 32) acc = fmaf(hs[d], dpl[(size_t)d * DF_], acc);
    #pragma unroll
    for (int o = 16; o > 0; o >>= 1) acc += __shfl_xor_sync(0xffffffffu, acc, o);
    if (lane == 0) out[(size_t)b * C_ + l * DF_ + w] = acc + yt[l * DF_ + w];
}

// ---------------- host launch ----------------
extern "C" void kernel_launch(void* const* d_in, const int* in_sizes, int n_in,
                              void* d_out, int out_size)
{
    const float* x       = (const float*)d_in[0];
    const float* y       = (const float*)d_in[1];
    const float* embed_W = (const float*)d_in[2];
    const float* embed_b = (const float*)d_in[3];
    const float* Wq      = (const float*)d_in[4];
    const float* Wk      = (const float*)d_in[5];
    const float* Wv      = (const float*)d_in[6];
    const float* bq      = (const float*)d_in[7];
    const float* bk      = (const float*)d_in[8];
    const float* bv      = (const float*)d_in[9];
    const float* Wo      = (const float*)d_in[10];
    const float* bo      = (const float*)d_in[11];
    const float* ln1_g   = (const float*)d_in[12];
    const float* ln1_b   = (const float*)d_in[13];
    const float* ln2_g   = (const float*)d_in[14];
    const float* ln2_b   = (const float*)d_in[15];
    const float* ln3_g   = (const float*)d_in[16];
    const float* ln3_b   = (const float*)d_in[17];
    const float* W1      = (const float*)d_in[18];
    const float* b1      = (const float*)d_in[19];
    const float* W2      = (const float*)d_in[20];
    const float* b2      = (const float*)d_in[21];
    const float* dp      = (const float*)d_in[22];
    const float* dbias   = (const float*)d_in[23];
    float* out = (float*)d_out;

    float *pt, *px2, *pt2, *px3, *ph, *pyt, *pbkv, *pdump;
    __half *pq16, *ps16, *pkv16, *pxh, *pmemh, *paoh, *pt2h, *pf1h;
    __half *pwemb, *pwkv, *pwo, *pw1, *pw2;
    cudaGetSymbolAddress((void**)&pt,    g_t);
    cudaGetSymbolAddress((void**)&px2,   g_x2);
    cudaGetSymbolAddress((void**)&pt2,   g_t2);
    cudaGetSymbolAddress((void**)&px3,   g_x3);
    cudaGetSymbolAddress((void**)&ph,    g_h);
    cudaGetSymbolAddress((void**)&pyt,   g_yt);
    cudaGetSymbolAddress((void**)&pbkv,  g_bkv);
    cudaGetSymbolAddress((void**)&pdump, g_ascdump);
    cudaGetSymbolAddress((void**)&pq16,  g_q16);
    cudaGetSymbolAddress((void**)&ps16,  g_s16);
    cudaGetSymbolAddress((void**)&pkv16, g_kv16);
    cudaGetSymbolAddress((void**)&pxh,   g_xh);
    cudaGetSymbolAddress((void**)&pmemh, g_memh);
    cudaGetSymbolAddress((void**)&paoh,  g_aoh);
    cudaGetSymbolAddress((void**)&pt2h,  g_t2h);
    cudaGetSymbolAddress((void**)&pf1h,  g_f1h);
    cudaGetSymbolAddress((void**)&pwemb, g_wemb);
    cudaGetSymbolAddress((void**)&pwkv,  g_wkv);
    cudaGetSymbolAddress((void**)&pwo,   g_wo);
    cudaGetSymbolAddress((void**)&pw1,   g_w1);
    cudaGetSymbolAddress((void**)&pw2,   g_w2);

    cudaFuncSetAttribute(gemm16<true, 0, true>,   cudaFuncAttributeMaxDynamicSharedMemorySize, GM_SMEM);
    cudaFuncSetAttribute(gemm16<false, 0, true>,  cudaFuncAttributeMaxDynamicSharedMemorySize, GM_SMEM);
    cudaFuncSetAttribute(gemm16<false, 0, false>, cudaFuncAttributeMaxDynamicSharedMemorySize, GM_SMEM);
    cudaFuncSetAttribute(gemm16<false, 2, true>,  cudaFuncAttributeMaxDynamicSharedMemorySize, GM_SMEM);
    cudaFuncSetAttribute(gemm16<false, 1, true>,  cudaFuncAttributeMaxDynamicSharedMemorySize, GM_SMEM);
    cudaFuncSetAttribute(attn_v_mma,              cudaFuncAttributeMaxDynamicSharedMemorySize, AV_SMEM);

    float* asc = (out_size >= B_ * C_ + B_ * L_ * S_) ? (out + B_ * C_) : pdump;

    // ---- operand conversion ----
    cvt_h16<<<(BS_ * F0_ / 4 + 255) / 256, 256>>>(x, pxh, BS_ * F0_ / 4);
    cvt_h16<<<(D_ * F0_ / 4 + 255) / 256, 256>>>(embed_W, pwemb, D_ * F0_ / 4);
    cvt_h16<<<(D_ * D_ / 4 + 255) / 256, 256>>>(Wk, pwkv, D_ * D_ / 4);
    cvt_h16<<<(D_ * D_ / 4 + 255) / 256, 256>>>(Wv, pwkv + (size_t)D_ * D_, D_ * D_ / 4);
    cvt_h16<<<(D_ * D_ / 4 + 255) / 256, 256>>>(Wo, pwo, D_ * D_ / 4);
    cvt_h16<<<(D_ * D_ / 4 + 255) / 256, 256>>>(W1, pw1, D_ * D_ / 4);
    cvt_h16<<<(D_ * D_ / 4 + 255) / 256, 256>>>(W2, pw2, D_ * D_ / 4);
    concat_bias<<<(NKV_ + 255) / 256, 256>>>(bk, bv, pbkv);

    // ---- batch-independent preamble ----
    ln_rows<<<L_, 256>>>(y, ln1_g, ln1_b, pt, 2.0f, nullptr);              // t = LN(2y)
    qproj<<<dim3(L_, D_ / 128), 128>>>(pt, Wq, bq, pq16);
    yterm_kernel<<<L_, 320>>>(y, dp, dbias, pyt);

    // ---- mem = relu(x @ We^T + eb) -> fp16 ----
    gemm16<true, 0, true><<<dim3(D_ / 128, BS_ / 128, 1), 128, GM_SMEM>>>(
        pxh, pwemb, embed_b, nullptr, nullptr, pmemh,
        F0_, F0_, F0_, D_, 0, 0, 0, 0, 0);

    // ---- fused K|V GEMM -> fp16 kv (pitch 1536) ----
    gemm16<false, 0, true><<<dim3(NKV_ / 128, BS_ / 128, 1), 128, GM_SMEM>>>(
        pmemh, pwkv, pbkv, nullptr, nullptr, pkv16,
        D_, D_, D_, NKV_, 0, 0, 0, 0, 0);

    // ---- scores: per (b,h) GEMM q16[h] x K^T -> s16 fp16 (padded rows) ----
    gemm16<false, 0, false><<<dim3(S_ / 128, 1, B_ * H_), 128, GM_SMEM>>>(
        pq16, pkv16, nullptr, nullptr, nullptr, ps16,
        HD_, HD_, NKV_, S_, 0,
        (size_t)LP_ * HD_, (size_t)S_ * NKV_, (size_t)HD_, (size_t)LP_ * S_);

    // ---- softmax (in place) + head-mean ----
    softmax_mean<<<dim3(L_, B_), 256>>>(ps16, asc);

    // ---- attn @ V -> ao fp16 ----
    attn_v_mma<<<B_ * H_, 128, AV_SMEM>>>(ps16, pkv16, paoh);

    // ---- out-proj + residual t[l], LN2 ----
    gemm16<false, 2, true><<<dim3(D_ / 128, BL_ / 128, 1), 128, GM_SMEM>>>(
        paoh, pwo, bo, pt, px2, nullptr,
        D_, D_, D_, D_, L_, 0, 0, 0, 0);
    ln_rows<<<BL_, 256>>>(px2, ln2_g, ln2_b, pt2, 1.0f, pt2h);

    // ---- FFN ----
    gemm16<true, 0, true><<<dim3(D_ / 128, BL_ / 128, 1), 128, GM_SMEM>>>(
        pt2h, pw1, b1, nullptr, nullptr, pf1h,
        D_, D_, D_, D_, 0, 0, 0, 0, 0);
    gemm16<false, 1, true><<<dim3(D_ / 128, BL_ / 128, 1), 128, GM_SMEM>>>(
        pf1h, pw2, b2, pt2, px3, nullptr,
        D_, D_, D_, D_, 0, 0, 0, 0, 0);
    ln_rows<<<BL_, 256>>>(px3, ln3_g, ln3_b, ph, 1.0f, nullptr);

    // ---- GroupFC logits ----
    logits_kernel<<<dim3(L_, B_), 320>>>(ph, dp, pyt, out);
}